// round 4
// baseline (speedup 1.0000x reference)
#include <cuda_runtime.h>
#include <cuda_bf16.h>
#include <math.h>

// ---------------------------------------------------------------------------
// TrustDiffuserModule — factored implementation.
//
// Math rewrite: mean_r (sQK_r^T)(sQK_r^T)^T V = Q * (s^2 * M * (Q^T V)),
// M = mean_r K_r^T K_r  (64x64 per head, computed once; K is step-invariant).
//
// Layout detail: the reference's o (B,R,H,N,hd) --reshape--> (B,R,N,C) is a
// RAW flatten: (h,n,d) -> flat = h*12608 + n*64 + d -> row flat/768, col
// flat%768 (heads/positions scrambled). Reproduced by writing Y in
// (B, H, N, hd)-contiguous order.
// ---------------------------------------------------------------------------

#define NROWS_M   1576          // 8*197
#define NROWS_ALL 3546          // 18*197
#define NROWS_R   1970          // 10*197
#define D         768
#define H1        192
#define H2        96
#define NH        12
#define HD        64
#define NSTEPS    3

constexpr size_t AL(size_t x) { return (x + 255) & ~size_t(255); }
constexpr size_t OFF_H    = 0;
constexpr size_t OFF_E    = OFF_H    + AL((size_t)NROWS_ALL * H1);
constexpr size_t OFF_MASK = OFF_E    + AL((size_t)NROWS_ALL * H2);
constexpr size_t OFF_K    = OFF_MASK + AL((size_t)NROWS_M);
constexpr size_t OFF_M    = OFF_K    + AL((size_t)NROWS_R * D);
constexpr size_t OFF_X    = OFF_M    + AL((size_t)NH * HD * HD);
constexpr size_t OFF_QV   = OFF_X    + AL((size_t)NROWS_M * D);
constexpr size_t OFF_P    = OFF_QV   + AL((size_t)NROWS_M * 2 * D);
constexpr size_t OFF_W    = OFF_P    + AL((size_t)96 * HD * HD);
constexpr size_t OFF_Y    = OFF_W    + AL((size_t)96 * HD * HD);
constexpr size_t OFF_Z    = OFF_Y    + AL((size_t)NROWS_M * D);
constexpr size_t SCRATCH  = OFF_Z    + AL((size_t)NROWS_M * D);

__device__ float g_scratch[SCRATCH];

#define HBUF  (g_scratch + OFF_H)
#define EBUF  (g_scratch + OFF_E)
#define MASKB (g_scratch + OFF_MASK)
#define KBUF  (g_scratch + OFF_K)
#define MBUF  (g_scratch + OFF_M)
#define XCUR  (g_scratch + OFF_X)
#define QVBUF (g_scratch + OFF_QV)
#define PBUF  (g_scratch + OFF_P)
#define WBUF  (g_scratch + OFF_W)
#define YBUF  (g_scratch + OFF_Y)
#define ZBUF  (g_scratch + OFF_Z)

enum Buf { EXT = 0, B_H, B_E, B_K, B_X, B_QV, B_Y, B_Z };
__device__ __forceinline__ float* bufPtr(int b, const float* ext) {
    switch (b) {
        case B_H:  return HBUF;
        case B_E:  return EBUF;
        case B_K:  return KBUF;
        case B_X:  return XCUR;
        case B_QV: return QVBUF;
        case B_Y:  return YBUF;
        case B_Z:  return ZBUF;
        default:   return (float*)ext;
    }
}

// ---------------------------------------------------------------------------
// Generic register-blocked SGEMM:  C[M,N] = A[M,K] @ B[K,N]  (+bias, +gelu)
// ---------------------------------------------------------------------------
template <int BM, int BN, int BK, int TM, int TN, bool BIAS, bool GELU>
__global__ void sgemm_kernel(const float* __restrict__ Aext, int Abuf,
                             const float* __restrict__ Bext,
                             const float* __restrict__ bias,
                             float* __restrict__ Cext, int Cbuf,
                             int M, int N, int K)
{
    const float* A = bufPtr(Abuf, Aext);
    const float* B = Bext;
    float* C = bufPtr(Cbuf, Cext);

    constexpr int NT = (BM / TM) * (BN / TN);
    __shared__ float As[BK][BM];
    __shared__ float Bs[BK][BN];

    const int tid = threadIdx.x;
    const int tx = tid % (BN / TN);
    const int ty = tid / (BN / TN);
    const int rowBase = blockIdx.y * BM;
    const int colBase = blockIdx.x * BN;

    float acc[TM][TN];
#pragma unroll
    for (int i = 0; i < TM; i++)
#pragma unroll
        for (int j = 0; j < TN; j++) acc[i][j] = 0.f;

    for (int k0 = 0; k0 < K; k0 += BK) {
#pragma unroll 4
        for (int i = tid; i < BM * BK; i += NT) {
            int m = i / BK, kk = i % BK;
            int gm = rowBase + m, gk = k0 + kk;
            As[kk][m] = (gm < M && gk < K) ? A[(size_t)gm * K + gk] : 0.f;
        }
#pragma unroll 4
        for (int i = tid; i < BK * BN; i += NT) {
            int kk = i / BN, n = i % BN;
            int gk = k0 + kk, gn = colBase + n;
            Bs[kk][n] = (gk < K && gn < N) ? B[(size_t)gk * N + gn] : 0.f;
        }
        __syncthreads();

#pragma unroll
        for (int kk = 0; kk < BK; kk++) {
            float a[TM], b[TN];
#pragma unroll
            for (int i = 0; i < TM; i++) a[i] = As[kk][ty * TM + i];
#pragma unroll
            for (int j = 0; j < TN; j++) b[j] = Bs[kk][tx * TN + j];
#pragma unroll
            for (int i = 0; i < TM; i++)
#pragma unroll
                for (int j = 0; j < TN; j++) acc[i][j] += a[i] * b[j];
        }
        __syncthreads();
    }

#pragma unroll
    for (int i = 0; i < TM; i++) {
        int gm = rowBase + ty * TM + i;
        if (gm >= M) continue;
#pragma unroll
        for (int j = 0; j < TN; j++) {
            int gn = colBase + tx * TN + j;
            if (gn >= N) continue;
            float v = acc[i][j];
            if (BIAS) v += bias[gn];
            if (GELU) v = 0.5f * v * (1.f + erff(v * 0.70710678118654752440f));
            C[(size_t)gm * N + gn] = v;
        }
    }
}

__device__ __forceinline__ float warpSum(float v) {
#pragma unroll
    for (int o = 16; o; o >>= 1) v += __shfl_down_sync(0xffffffffu, v, o);
    return v;
}

// ---------------------------------------------------------------------------
// Projector mask: cosine of enc(x) row vs the 10 enc(ref) rows at same n.
// ---------------------------------------------------------------------------
__global__ void mask_kernel()
{
    const float* E = EBUF;
    const int idx = blockIdx.x;            // b*197+n
    const int n = idx % 197;
    const int lane = threadIdx.x;
    const float* ex = E + (size_t)idx * H2;

    float ex0 = ex[lane], ex1 = ex[lane + 32], ex2 = ex[lane + 64];
    float s = ex0 * ex0 + ex1 * ex1 + ex2 * ex2;
    s = warpSum(s);
    float nx = fmaxf(sqrtf(s), 1e-8f);
    nx = __shfl_sync(0xffffffffu, nx, 0);

    float csum = 0.f;
#pragma unroll
    for (int r = 0; r < 10; r++) {
        const float* er = E + (size_t)(NROWS_M + r * 197 + n) * H2;
        float e0 = er[lane], e1 = er[lane + 32], e2 = er[lane + 64];
        float d  = ex0 * e0 + ex1 * e1 + ex2 * e2;
        float n2 = e0 * e0 + e1 * e1 + e2 * e2;
        d  = warpSum(d);
        n2 = warpSum(n2);
        if (lane == 0) {
            float nr = fmaxf(sqrtf(n2), 1e-8f);
            csum += d / (nx * nr);
        }
    }
    if (lane == 0) {
        float c = (csum * 0.1f + 1.f) * 0.5f;
        MASKB[idx] = 0.5f + 0.5f * tanhf(25.f * (c - 0.5f));
    }
}

// ---------------------------------------------------------------------------
// Gram: M_h = (1/10) * sum_n K[n, h*64:(h+1)*64]^T K[n, ...]
// ---------------------------------------------------------------------------
__global__ void gram_kernel()
{
    const float* Kb = KBUF;
    const int h = blockIdx.x;
    __shared__ float Ks[32][HD];
    const int tid = threadIdx.x;
    const int tj = tid % 16, ti = tid / 16;
    float acc[4][4] = {};

    for (int n0 = 0; n0 < NROWS_R; n0 += 32) {
        for (int i = tid; i < 32 * HD; i += 256) {
            int r = i / HD, c = i % HD;
            int n = n0 + r;
            Ks[r][c] = (n < NROWS_R) ? Kb[(size_t)n * D + h * HD + c] : 0.f;
        }
        __syncthreads();
#pragma unroll
        for (int r = 0; r < 32; r++) {
            float a[4], b[4];
#pragma unroll
            for (int i = 0; i < 4; i++) a[i] = Ks[r][ti * 4 + i];
#pragma unroll
            for (int j = 0; j < 4; j++) b[j] = Ks[r][tj * 4 + j];
#pragma unroll
            for (int i = 0; i < 4; i++)
#pragma unroll
                for (int j = 0; j < 4; j++) acc[i][j] += a[i] * b[j];
        }
        __syncthreads();
    }
#pragma unroll
    for (int i = 0; i < 4; i++)
#pragma unroll
        for (int j = 0; j < 4; j++)
            MBUF[(size_t)h * HD * HD + (ti * 4 + i) * HD + (tj * 4 + j)] = acc[i][j] * 0.1f;
}

// ---------------------------------------------------------------------------
// P[b,h] = Q[b,h]^T V[b,h]  (64x64, inner 197). One block per (b,h).
// ---------------------------------------------------------------------------
__global__ void qtv_kernel()
{
    const float* QV = QVBUF;
    const int bh = blockIdx.x;
    const int b = bh / NH, h = bh % NH;
    __shared__ float Qs[32][HD];
    __shared__ float Vs[32][HD];
    const int tid = threadIdx.x;
    const int tj = tid % 16, ti = tid / 16;
    float acc[4][4] = {};

    for (int n0 = 0; n0 < 197; n0 += 32) {
        for (int i = tid; i < 32 * HD; i += 256) {
            int r = i / HD, c = i % HD;
            int n = n0 + r;
            float q = 0.f, v = 0.f;
            if (n < 197) {
                size_t base = (size_t)(b * 197 + n) * (2 * D) + h * HD + c;
                q = QV[base];
                v = QV[base + D];
            }
            Qs[r][c] = q;
            Vs[r][c] = v;
        }
        __syncthreads();
#pragma unroll
        for (int r = 0; r < 32; r++) {
            float a[4], bv[4];
#pragma unroll
            for (int i = 0; i < 4; i++) a[i] = Qs[r][ti * 4 + i];
#pragma unroll
            for (int j = 0; j < 4; j++) bv[j] = Vs[r][tj * 4 + j];
#pragma unroll
            for (int i = 0; i < 4; i++)
#pragma unroll
                for (int j = 0; j < 4; j++) acc[i][j] += a[i] * bv[j];
        }
        __syncthreads();
    }
#pragma unroll
    for (int i = 0; i < 4; i++)
#pragma unroll
        for (int j = 0; j < 4; j++)
            PBUF[(size_t)bh * HD * HD + (ti * 4 + i) * HD + (tj * 4 + j)] = acc[i][j];
}

// ---------------------------------------------------------------------------
// W[b,h] = (1/64) * M_h @ P[b,h]  (64x64x64).
// ---------------------------------------------------------------------------
__global__ void wmat_kernel()
{
    const int bh = blockIdx.x;
    const int h = bh % NH;
    __shared__ float Ms[HD][HD];
    __shared__ float Ps[HD][HD];
    const int tid = threadIdx.x;
    for (int i = tid; i < HD * HD; i += 256) {
        Ms[i / HD][i % HD] = MBUF[(size_t)h * HD * HD + i];
        Ps[i / HD][i % HD] = PBUF[(size_t)bh * HD * HD + i];
    }
    __syncthreads();
    const int tj = tid % 16, ti = tid / 16;
    float acc[4][4] = {};
#pragma unroll 8
    for (int k = 0; k < HD; k++) {
        float a[4], b[4];
#pragma unroll
        for (int i = 0; i < 4; i++) a[i] = Ms[ti * 4 + i][k];
#pragma unroll
        for (int j = 0; j < 4; j++) b[j] = Ps[k][tj * 4 + j];
#pragma unroll
        for (int i = 0; i < 4; i++)
#pragma unroll
            for (int j = 0; j < 4; j++) acc[i][j] += a[i] * b[j];
    }
#pragma unroll
    for (int i = 0; i < 4; i++)
#pragma unroll
        for (int j = 0; j < 4; j++)
            WBUF[(size_t)bh * HD * HD + (ti * 4 + i) * HD + (tj * 4 + j)] =
                acc[i][j] * (1.f / 64.f);
}

// ---------------------------------------------------------------------------
// Y write reproduces the reference's raw reshape:
//   value(b, h, n, j) -> YBUF[b*197*768 + h*197*64 + n*64 + j]
// ---------------------------------------------------------------------------
__global__ void qw_kernel()
{
    const float* QV = QVBUF;
    const int bh = blockIdx.x;
    const int b = bh / NH, h = bh % NH;
    __shared__ float Ws[HD][HD];
    const int tid = threadIdx.x;
    for (int i = tid; i < HD * HD; i += 256)
        Ws[i / HD][i % HD] = WBUF[(size_t)bh * HD * HD + i];
    __syncthreads();

    const int lr = tid / 8;
    const int lc = (tid % 8) * 8;
    const int n = blockIdx.y * 32 + lr;
    if (n >= 197) return;

    const float* qrow = QV + (size_t)(b * 197 + n) * (2 * D) + h * HD;
    float acc[8] = {};
#pragma unroll 8
    for (int d = 0; d < HD; d++) {
        float q = qrow[d];
#pragma unroll
        for (int j = 0; j < 8; j++) acc[j] += q * Ws[d][lc + j];
    }
    // scrambled (reference reshape) layout: (B, H, N, hd) contiguous
    float* yrow = YBUF + (size_t)b * (197 * D) + (size_t)h * (197 * HD)
                       + (size_t)n * HD + lc;
#pragma unroll
    for (int j = 0; j < 8; j++) yrow[j] = acc[j];
}

// ---------------------------------------------------------------------------
// LayerNorm over last dim (768). One block of 256 per row. Z -> Xcur.
// ---------------------------------------------------------------------------
__global__ void ln_kernel(const float* __restrict__ g, const float* __restrict__ b)
{
    const int row = blockIdx.x;
    const float* z = ZBUF + (size_t)row * D;
    const int t = threadIdx.x;
    float v0 = z[t], v1 = z[t + 256], v2 = z[t + 512];
    float s = v0 + v1 + v2;
    float ss = v0 * v0 + v1 * v1 + v2 * v2;

    __shared__ float sh1[8], sh2[8];
    const int lane = t & 31, w = t >> 5;
    s = warpSum(s);
    ss = warpSum(ss);
    if (lane == 0) { sh1[w] = s; sh2[w] = ss; }
    __syncthreads();
    if (w == 0) {
        float a = lane < 8 ? sh1[lane] : 0.f;
        float c = lane < 8 ? sh2[lane] : 0.f;
        a = warpSum(a);
        c = warpSum(c);
        if (lane == 0) { sh1[0] = a; sh2[0] = c; }
    }
    __syncthreads();
    const float mu = sh1[0] * (1.f / 768.f);
    const float var = sh2[0] * (1.f / 768.f) - mu * mu;
    const float inv = rsqrtf(var + 1e-5f);
    float* o = XCUR + (size_t)row * D;
    o[t]       = (v0 - mu) * inv * g[t]       + b[t];
    o[t + 256] = (v1 - mu) * inv * g[t + 256] + b[t + 256];
    o[t + 512] = (v2 - mu) * inv * g[t + 512] + b[t + 512];
}

// ---------------------------------------------------------------------------
// Elementwise: x0 = xm * mask ; final = m*corrected + (1-m)*xm
// ---------------------------------------------------------------------------
__global__ void maskmul_kernel(const float* __restrict__ x)
{
    int i = blockIdx.x * blockDim.x + threadIdx.x;
    if (i < NROWS_M * D) XCUR[i] = x[i] * MASKB[i / D];
}

__global__ void blend_kernel(const float* __restrict__ x, float* __restrict__ out)
{
    int i = blockIdx.x * blockDim.x + threadIdx.x;
    if (i < NROWS_M * D) {
        float m = MASKB[i / D];
        out[i] = m * XCUR[i] + (1.f - m) * x[i];
    }
}

// ---------------------------------------------------------------------------
// Launch — kernels only + one D2D memcpyAsync. No other CUDA APIs.
// ---------------------------------------------------------------------------
extern "C" void kernel_launch(void* const* d_in, const int* in_sizes, int n_in,
                              void* d_out, int out_size)
{
    const float* x      = (const float*)d_in[0];
    const float* qv_w   = (const float*)d_in[1];
    const float* k_w    = (const float*)d_in[2];
    const float* proj_w = (const float*)d_in[3];
    const float* proj_b = (const float*)d_in[4];
    const float* ln_g   = (const float*)d_in[5];
    const float* ln_b   = (const float*)d_in[6];
    const float* fc1_w  = (const float*)d_in[7];
    const float* fc1_b  = (const float*)d_in[8];
    const float* fc2_w  = (const float*)d_in[9];
    const float* fc2_b  = (const float*)d_in[10];
    float* out = (float*)d_out;

    const float* ref = x + (size_t)NROWS_M * D;

    // refs pass through to output rows 1576..3545
    cudaMemcpyAsync(out + (size_t)NROWS_M * D, ref,
                    (size_t)NROWS_R * D * sizeof(float),
                    cudaMemcpyDeviceToDevice, 0);

    // --- projector encoder (all 18 batches at once) ---
    {   // H = gelu(x @ fc1_w + fc1_b)   (3546 x 192)
        dim3 grid((H1 + 63) / 64, (NROWS_ALL + 127) / 128);
        sgemm_kernel<128, 64, 8, 8, 4, true, true><<<grid, 256>>>(
            x, EXT, fc1_w, fc1_b, nullptr, B_H, NROWS_ALL, H1, D);
    }
    {   // E = H @ fc2_w + fc2_b   (3546 x 96)
        dim3 grid((H2 + 63) / 64, (NROWS_ALL + 127) / 128);
        sgemm_kernel<128, 64, 8, 8, 4, true, false><<<grid, 256>>>(
            nullptr, B_H, fc2_w, fc2_b, nullptr, B_E, NROWS_ALL, H2, H1);
    }
    mask_kernel<<<NROWS_M, 32>>>();

    // --- K projection + per-head Gram matrices (step-invariant) ---
    {
        dim3 grid((D + 63) / 64, (NROWS_R + 127) / 128);
        sgemm_kernel<128, 64, 8, 8, 4, false, false><<<grid, 256>>>(
            ref, EXT, k_w, nullptr, nullptr, B_K, NROWS_R, D, D);
    }
    gram_kernel<<<NH, 256>>>();

    // --- x0 = xm * mask ---
    maskmul_kernel<<<(NROWS_M * D + 255) / 256, 256>>>(x);

    // --- 3 diffuser steps ---
    for (int step = 0; step < NSTEPS; step++) {
        {   // QV = Xcur @ qv_w  (1576 x 1536)
            dim3 grid((2 * D + 127) / 128, (NROWS_M + 127) / 128);
            sgemm_kernel<128, 128, 8, 8, 8, false, false><<<grid, 256>>>(
                nullptr, B_X, qv_w, nullptr, nullptr, B_QV, NROWS_M, 2 * D, D);
        }
        qtv_kernel<<<8 * NH, 256>>>();
        wmat_kernel<<<8 * NH, 256>>>();
        qw_kernel<<<dim3(8 * NH, 7), 256>>>();
        {   // Z = Y @ proj_w + proj_b  (NO activation — feeds layernorm)
            dim3 grid((D + 63) / 64, (NROWS_M + 127) / 128);
            sgemm_kernel<128, 64, 8, 8, 4, true, false><<<grid, 256>>>(
                nullptr, B_Y, proj_w, proj_b, nullptr, B_Z, NROWS_M, D, D);
        }
        ln_kernel<<<NROWS_M, 256>>>(ln_g, ln_b);
    }

    // --- final blend ---
    blend_kernel<<<(NROWS_M * D + 255) / 256, 256>>>(x, out);
}

// round 5
// speedup vs baseline: 1.7747x; 1.7747x over previous
#include <cuda_runtime.h>
#include <cuda_bf16.h>
#include <math.h>

// ---------------------------------------------------------------------------
// TrustDiffuserModule — factored implementation, round 5: double-buffered
// vectorized SGEMM + qtv/wmat fusion.
//
// Math rewrite: mean_r (sQK_r^T)(sQK_r^T)^T V = Q * (s^2 * M * (Q^T V)),
// M = mean_r K_r^T K_r  (64x64 per head, computed once; K step-invariant).
//
// Reference's o (B,R,H,N,hd) -> reshape (B,R,N,C) is a RAW flatten
// (heads/positions scrambled): reproduced by writing Y (B,H,N,hd)-contiguous.
// ---------------------------------------------------------------------------

#define NROWS_M   1576          // 8*197
#define NROWS_ALL 3546          // 18*197
#define NROWS_R   1970          // 10*197
#define D         768
#define H1        192
#define H2        96
#define NH        12
#define HD        64
#define NSTEPS    3

constexpr size_t AL(size_t x) { return (x + 255) & ~size_t(255); }
constexpr size_t OFF_H    = 0;
constexpr size_t OFF_E    = OFF_H    + AL((size_t)NROWS_ALL * H1);
constexpr size_t OFF_MASK = OFF_E    + AL((size_t)NROWS_ALL * H2);
constexpr size_t OFF_K    = OFF_MASK + AL((size_t)NROWS_M);
constexpr size_t OFF_M    = OFF_K    + AL((size_t)NROWS_R * D);
constexpr size_t OFF_X    = OFF_M    + AL((size_t)NH * HD * HD);
constexpr size_t OFF_QV   = OFF_X    + AL((size_t)NROWS_M * D);
constexpr size_t OFF_W    = OFF_QV   + AL((size_t)NROWS_M * 2 * D);
constexpr size_t OFF_Y    = OFF_W    + AL((size_t)96 * HD * HD);
constexpr size_t OFF_Z    = OFF_Y    + AL((size_t)NROWS_M * D);
// pad generously so partial-tile GEMM stores can never touch a neighbor
constexpr size_t SCRATCH  = OFF_Z    + AL((size_t)NROWS_M * D) + 128 * 2048;

__device__ float g_scratch[SCRATCH];

#define HBUF  (g_scratch + OFF_H)
#define EBUF  (g_scratch + OFF_E)
#define MASKB (g_scratch + OFF_MASK)
#define KBUF  (g_scratch + OFF_K)
#define MBUF  (g_scratch + OFF_M)
#define XCUR  (g_scratch + OFF_X)
#define QVBUF (g_scratch + OFF_QV)
#define WBUF  (g_scratch + OFF_W)
#define YBUF  (g_scratch + OFF_Y)
#define ZBUF  (g_scratch + OFF_Z)

enum Buf { EXT = 0, B_H, B_E, B_K, B_X, B_QV, B_Y, B_Z };
__device__ __forceinline__ float* bufPtr(int b, const float* ext) {
    switch (b) {
        case B_H:  return HBUF;
        case B_E:  return EBUF;
        case B_K:  return KBUF;
        case B_X:  return XCUR;
        case B_QV: return QVBUF;
        case B_Y:  return YBUF;
        case B_Z:  return ZBUF;
        default:   return (float*)ext;
    }
}

// ---------------------------------------------------------------------------
// Double-buffered vectorized SGEMM: C[M,N] = A[M,K] @ B[K,N] (+bias, +gelu)
// Fixed geometry: BM=128, BN=64, BK=16, TM=8, TN=4, 256 threads.
// Requires K % 16 == 0 (true for all call sites: 768/192).
// ---------------------------------------------------------------------------
template <bool BIAS, bool GELU>
__global__ __launch_bounds__(256)
void sgemm_kernel(const float* __restrict__ Aext, int Abuf,
                  const float* __restrict__ B,
                  const float* __restrict__ bias,
                  float* __restrict__ Cext, int Cbuf,
                  int M, int N, int K)
{
    constexpr int BM = 128, BN = 64, BK = 16;
    const float* A = bufPtr(Abuf, Aext);
    float* C = bufPtr(Cbuf, Cext);

    __shared__ float As[2][BK][BM + 4];
    __shared__ float Bs[2][BK][BN];

    const int tid = threadIdx.x;
    const int rowBase = blockIdx.y * BM;
    const int colBase = blockIdx.x * BN;
    const int ty = tid >> 4;           // 0..15  (rows ty*8..+7)
    const int tx = tid & 15;           // 0..15  (cols tx*4..+3)

    // A loader: 2 float4 per thread along k
    const int am0 = tid >> 2;          // 0..63
    const int ak  = (tid & 3) * 4;     // 0,4,8,12
    const int am1 = am0 + 64;
    // B loader: 1 float4 per thread along n
    const int bk = tid >> 4;           // 0..15
    const int bn = (tid & 15) * 4;     // 0..60

    const bool fullM = (rowBase + BM <= M);
    const bool fullN = (colBase + BN <= N);
    const int nt = K / BK;

    float acc[8][4] = {};
    float4 pa0, pa1, pb;

    auto loadTile = [&](int t) {
        const int k0 = t * BK;
        if (fullM) {
            pa0 = *(const float4*)&A[(size_t)(rowBase + am0) * K + k0 + ak];
            pa1 = *(const float4*)&A[(size_t)(rowBase + am1) * K + k0 + ak];
        } else {
            pa0 = make_float4(0.f, 0.f, 0.f, 0.f);
            pa1 = pa0;
            if (rowBase + am0 < M)
                pa0 = *(const float4*)&A[(size_t)(rowBase + am0) * K + k0 + ak];
            if (rowBase + am1 < M)
                pa1 = *(const float4*)&A[(size_t)(rowBase + am1) * K + k0 + ak];
        }
        if (fullN) {
            pb = *(const float4*)&B[(size_t)(k0 + bk) * N + colBase + bn];
        } else {
            const float* brow = &B[(size_t)(k0 + bk) * N];
            float t0 = (colBase + bn + 0 < N) ? brow[colBase + bn + 0] : 0.f;
            float t1 = (colBase + bn + 1 < N) ? brow[colBase + bn + 1] : 0.f;
            float t2 = (colBase + bn + 2 < N) ? brow[colBase + bn + 2] : 0.f;
            float t3 = (colBase + bn + 3 < N) ? brow[colBase + bn + 3] : 0.f;
            pb = make_float4(t0, t1, t2, t3);
        }
    };
    auto storeTile = [&](int buf) {
        As[buf][ak + 0][am0] = pa0.x; As[buf][ak + 1][am0] = pa0.y;
        As[buf][ak + 2][am0] = pa0.z; As[buf][ak + 3][am0] = pa0.w;
        As[buf][ak + 0][am1] = pa1.x; As[buf][ak + 1][am1] = pa1.y;
        As[buf][ak + 2][am1] = pa1.z; As[buf][ak + 3][am1] = pa1.w;
        *(float4*)&Bs[buf][bk][bn] = pb;
    };

    loadTile(0);
    storeTile(0);
    __syncthreads();

    int buf = 0;
    for (int t = 0; t < nt; t++) {
        if (t + 1 < nt) loadTile(t + 1);
#pragma unroll
        for (int k = 0; k < BK; k++) {
            float4 a0 = *(const float4*)&As[buf][k][ty * 8];
            float4 a1 = *(const float4*)&As[buf][k][ty * 8 + 4];
            float4 b0 = *(const float4*)&Bs[buf][k][tx * 4];
            float a[8] = {a0.x, a0.y, a0.z, a0.w, a1.x, a1.y, a1.z, a1.w};
            float bb[4] = {b0.x, b0.y, b0.z, b0.w};
#pragma unroll
            for (int i = 0; i < 8; i++)
#pragma unroll
                for (int j = 0; j < 4; j++)
                    acc[i][j] += a[i] * bb[j];
        }
        if (t + 1 < nt) {
            storeTile(buf ^ 1);
            __syncthreads();
            buf ^= 1;
        }
    }

#pragma unroll
    for (int i = 0; i < 8; i++) {
        int gm = rowBase + ty * 8 + i;
        if (gm >= M) continue;
#pragma unroll
        for (int j = 0; j < 4; j++) {
            int gn = colBase + tx * 4 + j;
            if (gn >= N) continue;
            float v = acc[i][j];
            if (BIAS) v += bias[gn];
            if (GELU) v = 0.5f * v * (1.f + erff(v * 0.70710678118654752440f));
            C[(size_t)gm * N + gn] = v;
        }
    }
}

__device__ __forceinline__ float warpSum(float v) {
#pragma unroll
    for (int o = 16; o; o >>= 1) v += __shfl_down_sync(0xffffffffu, v, o);
    return v;
}

// ---------------------------------------------------------------------------
// Projector mask: cosine of enc(x) row vs the 10 enc(ref) rows at same n.
// ---------------------------------------------------------------------------
__global__ void mask_kernel()
{
    const float* E = EBUF;
    const int idx = blockIdx.x;            // b*197+n
    const int n = idx % 197;
    const int lane = threadIdx.x;
    const float* ex = E + (size_t)idx * H2;

    float ex0 = ex[lane], ex1 = ex[lane + 32], ex2 = ex[lane + 64];
    float s = ex0 * ex0 + ex1 * ex1 + ex2 * ex2;
    s = warpSum(s);
    float nx = fmaxf(sqrtf(s), 1e-8f);
    nx = __shfl_sync(0xffffffffu, nx, 0);

    float csum = 0.f;
#pragma unroll
    for (int r = 0; r < 10; r++) {
        const float* er = E + (size_t)(NROWS_M + r * 197 + n) * H2;
        float e0 = er[lane], e1 = er[lane + 32], e2 = er[lane + 64];
        float d  = ex0 * e0 + ex1 * e1 + ex2 * e2;
        float n2 = e0 * e0 + e1 * e1 + e2 * e2;
        d  = warpSum(d);
        n2 = warpSum(n2);
        if (lane == 0) {
            float nr = fmaxf(sqrtf(n2), 1e-8f);
            csum += d / (nx * nr);
        }
    }
    if (lane == 0) {
        float c = (csum * 0.1f + 1.f) * 0.5f;
        MASKB[idx] = 0.5f + 0.5f * tanhf(25.f * (c - 0.5f));
    }
}

// ---------------------------------------------------------------------------
// Gram: M_h = (1/10) * sum_n K[n, h*64:(h+1)*64]^T K[n, ...]
// ---------------------------------------------------------------------------
__global__ void gram_kernel()
{
    const float* Kb = KBUF;
    const int h = blockIdx.x;
    __shared__ float Ks[32][HD];
    const int tid = threadIdx.x;
    const int tj = tid % 16, ti = tid / 16;
    float acc[4][4] = {};

    for (int n0 = 0; n0 < NROWS_R; n0 += 32) {
        for (int i = tid; i < 32 * HD; i += 256) {
            int r = i / HD, c = i % HD;
            int n = n0 + r;
            Ks[r][c] = (n < NROWS_R) ? Kb[(size_t)n * D + h * HD + c] : 0.f;
        }
        __syncthreads();
#pragma unroll
        for (int r = 0; r < 32; r++) {
            float a[4], b[4];
#pragma unroll
            for (int i = 0; i < 4; i++) a[i] = Ks[r][ti * 4 + i];
#pragma unroll
            for (int j = 0; j < 4; j++) b[j] = Ks[r][tj * 4 + j];
#pragma unroll
            for (int i = 0; i < 4; i++)
#pragma unroll
                for (int j = 0; j < 4; j++) acc[i][j] += a[i] * b[j];
        }
        __syncthreads();
    }
#pragma unroll
    for (int i = 0; i < 4; i++)
#pragma unroll
        for (int j = 0; j < 4; j++)
            MBUF[(size_t)h * HD * HD + (ti * 4 + i) * HD + (tj * 4 + j)] = acc[i][j] * 0.1f;
}

// ---------------------------------------------------------------------------
// Fused: P = Q^T V (inner 197), then W = (1/64) * M_h @ P, all in one block.
// One block per (b,h). P lives only in smem.
// ---------------------------------------------------------------------------
__global__ __launch_bounds__(256) void qtv_wmat_kernel()
{
    const float* QV = QVBUF;
    const int bh = blockIdx.x;
    const int b = bh / NH, h = bh % NH;
    __shared__ float Qs[32][HD];
    __shared__ float Vs[32][HD];
    __shared__ float Ps[HD][HD];
    __shared__ float Ms[HD][HD];
    const int tid = threadIdx.x;
    const int tj = tid % 16, ti = tid / 16;
    float acc[4][4] = {};

    for (int n0 = 0; n0 < 197; n0 += 32) {
        for (int i = tid; i < 32 * HD; i += 256) {
            int r = i / HD, c = i % HD;
            int n = n0 + r;
            float q = 0.f, v = 0.f;
            if (n < 197) {
                size_t base = (size_t)(b * 197 + n) * (2 * D) + h * HD + c;
                q = QV[base];
                v = QV[base + D];
            }
            Qs[r][c] = q;
            Vs[r][c] = v;
        }
        __syncthreads();
#pragma unroll
        for (int r = 0; r < 32; r++) {
            float a[4], bv[4];
#pragma unroll
            for (int i = 0; i < 4; i++) a[i] = Qs[r][ti * 4 + i];
#pragma unroll
            for (int j = 0; j < 4; j++) bv[j] = Vs[r][tj * 4 + j];
#pragma unroll
            for (int i = 0; i < 4; i++)
#pragma unroll
                for (int j = 0; j < 4; j++) acc[i][j] += a[i] * bv[j];
        }
        __syncthreads();
    }

    // stage P into smem, bring in M_h
#pragma unroll
    for (int i = 0; i < 4; i++)
#pragma unroll
        for (int j = 0; j < 4; j++)
            Ps[ti * 4 + i][tj * 4 + j] = acc[i][j];
    for (int i = tid; i < HD * HD; i += 256)
        Ms[i >> 6][i & 63] = MBUF[(size_t)h * HD * HD + i];
    __syncthreads();

    // W = (1/64) * Ms @ Ps
    float w[4][4] = {};
#pragma unroll 8
    for (int k = 0; k < HD; k++) {
        float a[4], bv[4];
#pragma unroll
        for (int i = 0; i < 4; i++) a[i] = Ms[ti * 4 + i][k];
#pragma unroll
        for (int j = 0; j < 4; j++) bv[j] = Ps[k][tj * 4 + j];
#pragma unroll
        for (int i = 0; i < 4; i++)
#pragma unroll
            for (int j = 0; j < 4; j++) w[i][j] += a[i] * bv[j];
    }
#pragma unroll
    for (int i = 0; i < 4; i++)
#pragma unroll
        for (int j = 0; j < 4; j++)
            WBUF[(size_t)bh * HD * HD + (ti * 4 + i) * HD + (tj * 4 + j)] =
                w[i][j] * (1.f / 64.f);
}

// ---------------------------------------------------------------------------
// Y write reproduces the reference's raw reshape:
//   value(b, h, n, j) -> YBUF[b*197*768 + h*197*64 + n*64 + j]
// ---------------------------------------------------------------------------
__global__ void qw_kernel()
{
    const float* QV = QVBUF;
    const int bh = blockIdx.x;
    const int b = bh / NH, h = bh % NH;
    __shared__ float Ws[HD][HD];
    const int tid = threadIdx.x;
    for (int i = tid; i < HD * HD; i += 256)
        Ws[i / HD][i % HD] = WBUF[(size_t)bh * HD * HD + i];
    __syncthreads();

    const int lr = tid / 8;
    const int lc = (tid % 8) * 8;
    const int n = blockIdx.y * 32 + lr;
    if (n >= 197) return;

    const float* qrow = QV + (size_t)(b * 197 + n) * (2 * D) + h * HD;
    float acc[8] = {};
#pragma unroll 8
    for (int d = 0; d < HD; d++) {
        float q = qrow[d];
#pragma unroll
        for (int j = 0; j < 8; j++) acc[j] += q * Ws[d][lc + j];
    }
    float* yrow = YBUF + (size_t)b * (197 * D) + (size_t)h * (197 * HD)
                       + (size_t)n * HD + lc;
#pragma unroll
    for (int j = 0; j < 8; j++) yrow[j] = acc[j];
}

// ---------------------------------------------------------------------------
// LayerNorm over last dim (768). One block of 256 per row. Z -> Xcur.
// ---------------------------------------------------------------------------
__global__ void ln_kernel(const float* __restrict__ g, const float* __restrict__ b)
{
    const int row = blockIdx.x;
    const float* z = ZBUF + (size_t)row * D;
    const int t = threadIdx.x;
    float v0 = z[t], v1 = z[t + 256], v2 = z[t + 512];
    float s = v0 + v1 + v2;
    float ss = v0 * v0 + v1 * v1 + v2 * v2;

    __shared__ float sh1[8], sh2[8];
    const int lane = t & 31, w = t >> 5;
    s = warpSum(s);
    ss = warpSum(ss);
    if (lane == 0) { sh1[w] = s; sh2[w] = ss; }
    __syncthreads();
    if (w == 0) {
        float a = lane < 8 ? sh1[lane] : 0.f;
        float c = lane < 8 ? sh2[lane] : 0.f;
        a = warpSum(a);
        c = warpSum(c);
        if (lane == 0) { sh1[0] = a; sh2[0] = c; }
    }
    __syncthreads();
    const float mu = sh1[0] * (1.f / 768.f);
    const float var = sh2[0] * (1.f / 768.f) - mu * mu;
    const float inv = rsqrtf(var + 1e-5f);
    float* o = XCUR + (size_t)row * D;
    o[t]       = (v0 - mu) * inv * g[t]       + b[t];
    o[t + 256] = (v1 - mu) * inv * g[t + 256] + b[t + 256];
    o[t + 512] = (v2 - mu) * inv * g[t + 512] + b[t + 512];
}

// ---------------------------------------------------------------------------
// Elementwise: x0 = xm * mask ; final = m*corrected + (1-m)*xm
// ---------------------------------------------------------------------------
__global__ void maskmul_kernel(const float* __restrict__ x)
{
    int i = blockIdx.x * blockDim.x + threadIdx.x;
    if (i < NROWS_M * D) XCUR[i] = x[i] * MASKB[i / D];
}

__global__ void blend_kernel(const float* __restrict__ x, float* __restrict__ out)
{
    int i = blockIdx.x * blockDim.x + threadIdx.x;
    if (i < NROWS_M * D) {
        float m = MASKB[i / D];
        out[i] = m * XCUR[i] + (1.f - m) * x[i];
    }
}

// ---------------------------------------------------------------------------
// Launch — kernels only + one D2D memcpyAsync.
// ---------------------------------------------------------------------------
extern "C" void kernel_launch(void* const* d_in, const int* in_sizes, int n_in,
                              void* d_out, int out_size)
{
    const float* x      = (const float*)d_in[0];
    const float* qv_w   = (const float*)d_in[1];
    const float* k_w    = (const float*)d_in[2];
    const float* proj_w = (const float*)d_in[3];
    const float* proj_b = (const float*)d_in[4];
    const float* ln_g   = (const float*)d_in[5];
    const float* ln_b   = (const float*)d_in[6];
    const float* fc1_w  = (const float*)d_in[7];
    const float* fc1_b  = (const float*)d_in[8];
    const float* fc2_w  = (const float*)d_in[9];
    const float* fc2_b  = (const float*)d_in[10];
    float* out = (float*)d_out;

    const float* ref = x + (size_t)NROWS_M * D;

    // refs pass through to output rows 1576..3545
    cudaMemcpyAsync(out + (size_t)NROWS_M * D, ref,
                    (size_t)NROWS_R * D * sizeof(float),
                    cudaMemcpyDeviceToDevice, 0);

    auto cdiv = [](int a, int b) { return (a + b - 1) / b; };

    // --- projector encoder (all 18 batches at once) ---
    sgemm_kernel<true, true><<<dim3(cdiv(H1, 64), cdiv(NROWS_ALL, 128)), 256>>>(
        x, EXT, fc1_w, fc1_b, nullptr, B_H, NROWS_ALL, H1, D);
    sgemm_kernel<true, false><<<dim3(cdiv(H2, 64), cdiv(NROWS_ALL, 128)), 256>>>(
        nullptr, B_H, fc2_w, fc2_b, nullptr, B_E, NROWS_ALL, H2, H1);
    mask_kernel<<<NROWS_M, 32>>>();

    // --- K projection + per-head Gram matrices (step-invariant) ---
    sgemm_kernel<false, false><<<dim3(cdiv(D, 64), cdiv(NROWS_R, 128)), 256>>>(
        ref, EXT, k_w, nullptr, nullptr, B_K, NROWS_R, D, D);
    gram_kernel<<<NH, 256>>>();

    // --- x0 = xm * mask ---
    maskmul_kernel<<<(NROWS_M * D + 255) / 256, 256>>>(x);

    // --- 3 diffuser steps ---
    for (int step = 0; step < NSTEPS; step++) {
        sgemm_kernel<false, false><<<dim3(cdiv(2 * D, 64), cdiv(NROWS_M, 128)), 256>>>(
            nullptr, B_X, qv_w, nullptr, nullptr, B_QV, NROWS_M, 2 * D, D);
        qtv_wmat_kernel<<<8 * NH, 256>>>();
        qw_kernel<<<dim3(8 * NH, 7), 256>>>();
        sgemm_kernel<true, false><<<dim3(cdiv(D, 64), cdiv(NROWS_M, 128)), 256>>>(
            nullptr, B_Y, proj_w, proj_b, nullptr, B_Z, NROWS_M, D, D);
        ln_kernel<<<NROWS_M, 256>>>(ln_g, ln_b);
    }

    // --- final blend ---
    blend_kernel<<<(NROWS_M * D + 255) / 256, 256>>>(x, out);
}

// round 7
// speedup vs baseline: 2.0399x; 1.1494x over previous
#include <cuda_runtime.h>
#include <cuda_bf16.h>
#include <math.h>
#include <cstdint>

// ---------------------------------------------------------------------------
// TrustDiffuserModule — round 7: tensor-core (mma.sync bf16 split-precision)
// GEMMs + factored attention.  (R6 + missing <cstdint> include.)
//
// Math rewrite: mean_r (sQK_r^T)(sQK_r^T)^T V = Q * (s^2 * M * (Q^T V)),
// M = mean_r K_r^T K_r (64x64/head, once). Reference's (B,R,H,N,hd)->(B,R,N,C)
// reshape is a raw flatten (scrambled); reproduced by (B,H,N,hd) writes.
//
// GEMM precision: fp32 operands split as a = ah + al (bf16 each);
// C = Ah*Bh + Ah*Bl + Al*Bh accumulated in fp32 -> ~1e-5 relative error.
// ---------------------------------------------------------------------------

#define NROWS_M   1576
#define NROWS_ALL 3546
#define NROWS_R   1970
#define D         768
#define H1        192
#define H2        96
#define NH        12
#define HD        64
#define NSTEPS    3

constexpr size_t AL(size_t x) { return (x + 255) & ~size_t(255); }
constexpr size_t OFF_H    = 0;
constexpr size_t OFF_E    = OFF_H    + AL((size_t)NROWS_ALL * H1);
constexpr size_t OFF_MASK = OFF_E    + AL((size_t)NROWS_ALL * H2);
constexpr size_t OFF_K    = OFF_MASK + AL((size_t)NROWS_M);
constexpr size_t OFF_M    = OFF_K    + AL((size_t)NROWS_R * D);
constexpr size_t OFF_X    = OFF_M    + AL((size_t)NH * HD * HD);
constexpr size_t OFF_QV   = OFF_X    + AL((size_t)NROWS_M * D);
constexpr size_t OFF_W    = OFF_QV   + AL((size_t)NROWS_M * 2 * D);
constexpr size_t OFF_Y    = OFF_W    + AL((size_t)96 * HD * HD);
constexpr size_t OFF_Z    = OFF_Y    + AL((size_t)NROWS_M * D);
constexpr size_t SCRATCH  = OFF_Z    + AL((size_t)NROWS_M * D) + 128 * 2048;

__device__ float g_scratch[SCRATCH];

#define HBUF  (g_scratch + OFF_H)
#define EBUF  (g_scratch + OFF_E)
#define MASKB (g_scratch + OFF_MASK)
#define KBUF  (g_scratch + OFF_K)
#define MBUF  (g_scratch + OFF_M)
#define XCUR  (g_scratch + OFF_X)
#define QVBUF (g_scratch + OFF_QV)
#define WBUF  (g_scratch + OFF_W)
#define YBUF  (g_scratch + OFF_Y)
#define ZBUF  (g_scratch + OFF_Z)

enum Buf { EXT = 0, B_H, B_E, B_K, B_X, B_QV, B_Y, B_Z };
__device__ __forceinline__ float* bufPtr(int b, const float* ext) {
    switch (b) {
        case B_H:  return HBUF;
        case B_E:  return EBUF;
        case B_K:  return KBUF;
        case B_X:  return XCUR;
        case B_QV: return QVBUF;
        case B_Y:  return YBUF;
        case B_Z:  return ZBUF;
        default:   return (float*)ext;
    }
}

// ---------------------------------------------------------------------------
// Tensor-core GEMM, split-precision bf16.  C[M,N] = A[M,K] @ B[K,N]
// BM=128, BN=128, BK=32, 256 threads (8 warps as 2x4 -> 64x32 warp tiles).
// Requires K % 32 == 0 (all call sites: 768 or 192).
// ---------------------------------------------------------------------------
__device__ __forceinline__ void cvt_split(float v, __nv_bfloat16& h, __nv_bfloat16& l) {
    h = __float2bfloat16(v);
    l = __float2bfloat16(v - __bfloat162float(h));
}
__device__ __forceinline__ uint32_t pack_bf2(__nv_bfloat16 x, __nv_bfloat16 y) {
    __nv_bfloat162 t;
    t.x = x; t.y = y;
    return *reinterpret_cast<uint32_t*>(&t);
}
__device__ __forceinline__ void mma_bf16(float* c, const uint32_t* a, const uint32_t* b) {
    asm volatile(
        "mma.sync.aligned.m16n8k16.row.col.f32.bf16.bf16.f32 "
        "{%0,%1,%2,%3}, {%4,%5,%6,%7}, {%8,%9}, {%0,%1,%2,%3};\n"
        : "+f"(c[0]), "+f"(c[1]), "+f"(c[2]), "+f"(c[3])
        : "r"(a[0]), "r"(a[1]), "r"(a[2]), "r"(a[3]), "r"(b[0]), "r"(b[1]));
}

template <bool BIAS, bool GELU>
__global__ __launch_bounds__(256)
void bgemm_kernel(const float* __restrict__ Aext, int Abuf,
                  const float* __restrict__ B,
                  const float* __restrict__ bias,
                  float* __restrict__ Cext, int Cbuf,
                  int M, int N, int K)
{
    constexpr int BM = 128, BN = 128, BK = 32;
    const float* A = bufPtr(Abuf, Aext);
    float* C = bufPtr(Cbuf, Cext);

    __shared__ __nv_bfloat16 Ah[BM][BK + 2], Al[BM][BK + 2];
    __shared__ __nv_bfloat16 Bh[BK][BN + 4], Bl[BK][BN + 4];

    const int tid  = threadIdx.x;
    const int wid  = tid >> 5;
    const int lane = tid & 31;
    const int g    = lane >> 2;       // 0..7
    const int t2   = (lane & 3) * 2;  // 0,2,4,6

    const int rowBase = blockIdx.y * BM;
    const int colBase = blockIdx.x * BN;
    const int warpRow = (wid >> 2) * 64;  // 0 or 64
    const int warpCol = (wid & 3) * 32;   // 0,32,64,96

    // stagers
    const int ar  = tid >> 3;         // 0..31
    const int akc = (tid & 7) * 4;    // 0..28
    const int bkr = tid >> 5;         // 0..7
    const int bnc = (tid & 31) * 4;   // 0..124

    const bool fullN = (colBase + BN <= N);

    float c[4][4][4];
#pragma unroll
    for (int mi = 0; mi < 4; mi++)
#pragma unroll
        for (int ni = 0; ni < 4; ni++)
#pragma unroll
            for (int e = 0; e < 4; e++) c[mi][ni][e] = 0.f;

    for (int k0 = 0; k0 < K; k0 += BK) {
        __syncthreads();   // WAR: previous compute done before overwrite
        // --- stage A (128x32) ---
#pragma unroll
        for (int p = 0; p < 4; p++) {
            int r = p * 32 + ar;
            int gm = rowBase + r;
            float4 v = make_float4(0.f, 0.f, 0.f, 0.f);
            if (gm < M) v = *(const float4*)&A[(size_t)gm * K + k0 + akc];
            __nv_bfloat16 h, l;
            cvt_split(v.x, h, l); Ah[r][akc + 0] = h; Al[r][akc + 0] = l;
            cvt_split(v.y, h, l); Ah[r][akc + 1] = h; Al[r][akc + 1] = l;
            cvt_split(v.z, h, l); Ah[r][akc + 2] = h; Al[r][akc + 2] = l;
            cvt_split(v.w, h, l); Ah[r][akc + 3] = h; Al[r][akc + 3] = l;
        }
        // --- stage B (32x128) ---
#pragma unroll
        for (int p = 0; p < 4; p++) {
            int kr = p * 8 + bkr;
            float4 v = make_float4(0.f, 0.f, 0.f, 0.f);
            if (fullN) {
                v = *(const float4*)&B[(size_t)(k0 + kr) * N + colBase + bnc];
            } else {
                const float* brow = &B[(size_t)(k0 + kr) * N];
                if (colBase + bnc + 0 < N) v.x = brow[colBase + bnc + 0];
                if (colBase + bnc + 1 < N) v.y = brow[colBase + bnc + 1];
                if (colBase + bnc + 2 < N) v.z = brow[colBase + bnc + 2];
                if (colBase + bnc + 3 < N) v.w = brow[colBase + bnc + 3];
            }
            __nv_bfloat16 h, l;
            cvt_split(v.x, h, l); Bh[kr][bnc + 0] = h; Bl[kr][bnc + 0] = l;
            cvt_split(v.y, h, l); Bh[kr][bnc + 1] = h; Bl[kr][bnc + 1] = l;
            cvt_split(v.z, h, l); Bh[kr][bnc + 2] = h; Bl[kr][bnc + 2] = l;
            cvt_split(v.w, h, l); Bh[kr][bnc + 3] = h; Bl[kr][bnc + 3] = l;
        }
        __syncthreads();

        // --- compute: 2 k-steps of 16 ---
#pragma unroll
        for (int ks = 0; ks < BK; ks += 16) {
            uint32_t ahf[4][4], alf[4][4], bhf[4][2], blf[4][2];
#pragma unroll
            for (int mi = 0; mi < 4; mi++) {
                int r0 = warpRow + mi * 16 + g;
                int r1 = r0 + 8;
                ahf[mi][0] = *(const uint32_t*)&Ah[r0][ks + t2];
                ahf[mi][1] = *(const uint32_t*)&Ah[r1][ks + t2];
                ahf[mi][2] = *(const uint32_t*)&Ah[r0][ks + t2 + 8];
                ahf[mi][3] = *(const uint32_t*)&Ah[r1][ks + t2 + 8];
                alf[mi][0] = *(const uint32_t*)&Al[r0][ks + t2];
                alf[mi][1] = *(const uint32_t*)&Al[r1][ks + t2];
                alf[mi][2] = *(const uint32_t*)&Al[r0][ks + t2 + 8];
                alf[mi][3] = *(const uint32_t*)&Al[r1][ks + t2 + 8];
            }
#pragma unroll
            for (int ni = 0; ni < 4; ni++) {
                int n = warpCol + ni * 8 + g;
                bhf[ni][0] = pack_bf2(Bh[ks + t2][n],     Bh[ks + t2 + 1][n]);
                bhf[ni][1] = pack_bf2(Bh[ks + t2 + 8][n], Bh[ks + t2 + 9][n]);
                blf[ni][0] = pack_bf2(Bl[ks + t2][n],     Bl[ks + t2 + 1][n]);
                blf[ni][1] = pack_bf2(Bl[ks + t2 + 8][n], Bl[ks + t2 + 9][n]);
            }
#pragma unroll
            for (int mi = 0; mi < 4; mi++)
#pragma unroll
                for (int ni = 0; ni < 4; ni++) {
                    mma_bf16(c[mi][ni], ahf[mi], bhf[ni]);
                    mma_bf16(c[mi][ni], ahf[mi], blf[ni]);
                    mma_bf16(c[mi][ni], alf[mi], bhf[ni]);
                }
        }
    }

    // --- epilogue ---
#pragma unroll
    for (int mi = 0; mi < 4; mi++) {
        int rm0 = rowBase + warpRow + mi * 16 + g;
        int rm1 = rm0 + 8;
#pragma unroll
        for (int ni = 0; ni < 4; ni++) {
            int cn = colBase + warpCol + ni * 8 + t2;
#pragma unroll
            for (int e = 0; e < 4; e++) {
                int gm = (e < 2) ? rm0 : rm1;
                int gn = cn + (e & 1);
                if (gm >= M || gn >= N) continue;
                float v = c[mi][ni][e];
                if (BIAS) v += bias[gn];
                if (GELU) v = 0.5f * v * (1.f + erff(v * 0.70710678118654752440f));
                C[(size_t)gm * N + gn] = v;
            }
        }
    }
}

__device__ __forceinline__ float warpSum(float v) {
#pragma unroll
    for (int o = 16; o; o >>= 1) v += __shfl_down_sync(0xffffffffu, v, o);
    return v;
}

// ---------------------------------------------------------------------------
// Projector mask
// ---------------------------------------------------------------------------
__global__ void mask_kernel()
{
    const float* E = EBUF;
    const int idx = blockIdx.x;
    const int n = idx % 197;
    const int lane = threadIdx.x;
    const float* ex = E + (size_t)idx * H2;

    float ex0 = ex[lane], ex1 = ex[lane + 32], ex2 = ex[lane + 64];
    float s = ex0 * ex0 + ex1 * ex1 + ex2 * ex2;
    s = warpSum(s);
    float nx = fmaxf(sqrtf(s), 1e-8f);
    nx = __shfl_sync(0xffffffffu, nx, 0);

    float csum = 0.f;
#pragma unroll
    for (int r = 0; r < 10; r++) {
        const float* er = E + (size_t)(NROWS_M + r * 197 + n) * H2;
        float e0 = er[lane], e1 = er[lane + 32], e2 = er[lane + 64];
        float d  = ex0 * e0 + ex1 * e1 + ex2 * e2;
        float n2 = e0 * e0 + e1 * e1 + e2 * e2;
        d  = warpSum(d);
        n2 = warpSum(n2);
        if (lane == 0) {
            float nr = fmaxf(sqrtf(n2), 1e-8f);
            csum += d / (nx * nr);
        }
    }
    if (lane == 0) {
        float c = (csum * 0.1f + 1.f) * 0.5f;
        MASKB[idx] = 0.5f + 0.5f * tanhf(25.f * (c - 0.5f));
    }
}

// ---------------------------------------------------------------------------
// Gram: M_h = (1/10) * sum_n K[n,h]^T K[n,h]
// ---------------------------------------------------------------------------
__global__ void gram_kernel()
{
    const float* Kb = KBUF;
    const int h = blockIdx.x;
    __shared__ float Ks[32][HD];
    const int tid = threadIdx.x;
    const int tj = tid % 16, ti = tid / 16;
    float acc[4][4] = {};

    for (int n0 = 0; n0 < NROWS_R; n0 += 32) {
        for (int i = tid; i < 32 * HD; i += 256) {
            int r = i / HD, c = i % HD;
            int n = n0 + r;
            Ks[r][c] = (n < NROWS_R) ? Kb[(size_t)n * D + h * HD + c] : 0.f;
        }
        __syncthreads();
#pragma unroll
        for (int r = 0; r < 32; r++) {
            float a[4], b[4];
#pragma unroll
            for (int i = 0; i < 4; i++) a[i] = Ks[r][ti * 4 + i];
#pragma unroll
            for (int j = 0; j < 4; j++) b[j] = Ks[r][tj * 4 + j];
#pragma unroll
            for (int i = 0; i < 4; i++)
#pragma unroll
                for (int j = 0; j < 4; j++) acc[i][j] += a[i] * b[j];
        }
        __syncthreads();
    }
#pragma unroll
    for (int i = 0; i < 4; i++)
#pragma unroll
        for (int j = 0; j < 4; j++)
            MBUF[(size_t)h * HD * HD + (ti * 4 + i) * HD + (tj * 4 + j)] = acc[i][j] * 0.1f;
}

// ---------------------------------------------------------------------------
// Fused: P = Q^T V (inner 197); W = (1/64) * M_h @ P.  One block per (b,h).
// ---------------------------------------------------------------------------
__global__ __launch_bounds__(256) void qtv_wmat_kernel()
{
    const float* QV = QVBUF;
    const int bh = blockIdx.x;
    const int b = bh / NH, h = bh % NH;
    __shared__ float Qs[32][HD];
    __shared__ float Vs[32][HD];
    __shared__ float Ps[HD][HD];
    __shared__ float Ms[HD][HD];
    const int tid = threadIdx.x;
    const int tj = tid % 16, ti = tid / 16;
    float acc[4][4] = {};

    for (int n0 = 0; n0 < 197; n0 += 32) {
        for (int i = tid; i < 32 * HD; i += 256) {
            int r = i / HD, c = i % HD;
            int n = n0 + r;
            float q = 0.f, v = 0.f;
            if (n < 197) {
                size_t base = (size_t)(b * 197 + n) * (2 * D) + h * HD + c;
                q = QV[base];
                v = QV[base + D];
            }
            Qs[r][c] = q;
            Vs[r][c] = v;
        }
        __syncthreads();
#pragma unroll
        for (int r = 0; r < 32; r++) {
            float a[4], bv[4];
#pragma unroll
            for (int i = 0; i < 4; i++) a[i] = Qs[r][ti * 4 + i];
#pragma unroll
            for (int j = 0; j < 4; j++) bv[j] = Vs[r][tj * 4 + j];
#pragma unroll
            for (int i = 0; i < 4; i++)
#pragma unroll
                for (int j = 0; j < 4; j++) acc[i][j] += a[i] * bv[j];
        }
        __syncthreads();
    }

#pragma unroll
    for (int i = 0; i < 4; i++)
#pragma unroll
        for (int j = 0; j < 4; j++)
            Ps[ti * 4 + i][tj * 4 + j] = acc[i][j];
    for (int i = tid; i < HD * HD; i += 256)
        Ms[i >> 6][i & 63] = MBUF[(size_t)h * HD * HD + i];
    __syncthreads();

    float w[4][4] = {};
#pragma unroll 8
    for (int k = 0; k < HD; k++) {
        float a[4], bv[4];
#pragma unroll
        for (int i = 0; i < 4; i++) a[i] = Ms[ti * 4 + i][k];
#pragma unroll
        for (int j = 0; j < 4; j++) bv[j] = Ps[k][tj * 4 + j];
#pragma unroll
        for (int i = 0; i < 4; i++)
#pragma unroll
            for (int j = 0; j < 4; j++) w[i][j] += a[i] * bv[j];
    }
#pragma unroll
    for (int i = 0; i < 4; i++)
#pragma unroll
        for (int j = 0; j < 4; j++)
            WBUF[(size_t)bh * HD * HD + (ti * 4 + i) * HD + (tj * 4 + j)] =
                w[i][j] * (1.f / 64.f);
}

// ---------------------------------------------------------------------------
// Y(b,h,n,:) = Q(b,h,n,:) @ W[b,h]; scrambled (B,H,N,hd) write.
// ---------------------------------------------------------------------------
__global__ void qw_kernel()
{
    const float* QV = QVBUF;
    const int bh = blockIdx.x;
    const int b = bh / NH, h = bh % NH;
    __shared__ float Ws[HD][HD];
    const int tid = threadIdx.x;
    for (int i = tid; i < HD * HD; i += 256)
        Ws[i / HD][i % HD] = WBUF[(size_t)bh * HD * HD + i];
    __syncthreads();

    const int lr = tid / 8;
    const int lc = (tid % 8) * 8;
    const int n = blockIdx.y * 32 + lr;
    if (n >= 197) return;

    const float* qrow = QV + (size_t)(b * 197 + n) * (2 * D) + h * HD;
    float acc[8] = {};
#pragma unroll 8
    for (int d = 0; d < HD; d++) {
        float q = qrow[d];
#pragma unroll
        for (int j = 0; j < 8; j++) acc[j] += q * Ws[d][lc + j];
    }
    float* yrow = YBUF + (size_t)b * (197 * D) + (size_t)h * (197 * HD)
                       + (size_t)n * HD + lc;
#pragma unroll
    for (int j = 0; j < 8; j++) yrow[j] = acc[j];
}

// ---------------------------------------------------------------------------
// LayerNorm (768). Z -> Xcur.
// ---------------------------------------------------------------------------
__global__ void ln_kernel(const float* __restrict__ g, const float* __restrict__ b)
{
    const int row = blockIdx.x;
    const float* z = ZBUF + (size_t)row * D;
    const int t = threadIdx.x;
    float v0 = z[t], v1 = z[t + 256], v2 = z[t + 512];
    float s = v0 + v1 + v2;
    float ss = v0 * v0 + v1 * v1 + v2 * v2;

    __shared__ float sh1[8], sh2[8];
    const int lane = t & 31, w = t >> 5;
    s = warpSum(s);
    ss = warpSum(ss);
    if (lane == 0) { sh1[w] = s; sh2[w] = ss; }
    __syncthreads();
    if (w == 0) {
        float a = lane < 8 ? sh1[lane] : 0.f;
        float c = lane < 8 ? sh2[lane] : 0.f;
        a = warpSum(a);
        c = warpSum(c);
        if (lane == 0) { sh1[0] = a; sh2[0] = c; }
    }
    __syncthreads();
    const float mu = sh1[0] * (1.f / 768.f);
    const float var = sh2[0] * (1.f / 768.f) - mu * mu;
    const float inv = rsqrtf(var + 1e-5f);
    float* o = XCUR + (size_t)row * D;
    o[t]       = (v0 - mu) * inv * g[t]       + b[t];
    o[t + 256] = (v1 - mu) * inv * g[t + 256] + b[t + 256];
    o[t + 512] = (v2 - mu) * inv * g[t + 512] + b[t + 512];
}

// ---------------------------------------------------------------------------
// Elementwise
// ---------------------------------------------------------------------------
__global__ void maskmul_kernel(const float* __restrict__ x)
{
    int i = blockIdx.x * blockDim.x + threadIdx.x;
    if (i < NROWS_M * D) XCUR[i] = x[i] * MASKB[i / D];
}

__global__ void blend_kernel(const float* __restrict__ x, float* __restrict__ out)
{
    int i = blockIdx.x * blockDim.x + threadIdx.x;
    if (i < NROWS_M * D) {
        float m = MASKB[i / D];
        out[i] = m * XCUR[i] + (1.f - m) * x[i];
    }
}

// ---------------------------------------------------------------------------
// Launch
// ---------------------------------------------------------------------------
extern "C" void kernel_launch(void* const* d_in, const int* in_sizes, int n_in,
                              void* d_out, int out_size)
{
    const float* x      = (const float*)d_in[0];
    const float* qv_w   = (const float*)d_in[1];
    const float* k_w    = (const float*)d_in[2];
    const float* proj_w = (const float*)d_in[3];
    const float* proj_b = (const float*)d_in[4];
    const float* ln_g   = (const float*)d_in[5];
    const float* ln_b   = (const float*)d_in[6];
    const float* fc1_w  = (const float*)d_in[7];
    const float* fc1_b  = (const float*)d_in[8];
    const float* fc2_w  = (const float*)d_in[9];
    const float* fc2_b  = (const float*)d_in[10];
    float* out = (float*)d_out;

    const float* ref = x + (size_t)NROWS_M * D;

    cudaMemcpyAsync(out + (size_t)NROWS_M * D, ref,
                    (size_t)NROWS_R * D * sizeof(float),
                    cudaMemcpyDeviceToDevice, 0);

    auto cdiv = [](int a, int b) { return (a + b - 1) / b; };

    // --- projector encoder ---
    bgemm_kernel<true, true><<<dim3(cdiv(H1, 128), cdiv(NROWS_ALL, 128)), 256>>>(
        x, EXT, fc1_w, fc1_b, nullptr, B_H, NROWS_ALL, H1, D);
    bgemm_kernel<true, false><<<dim3(cdiv(H2, 128), cdiv(NROWS_ALL, 128)), 256>>>(
        nullptr, B_H, fc2_w, fc2_b, nullptr, B_E, NROWS_ALL, H2, H1);
    mask_kernel<<<NROWS_M, 32>>>();

    // --- K projection + Gram ---
    bgemm_kernel<false, false><<<dim3(cdiv(D, 128), cdiv(NROWS_R, 128)), 256>>>(
        ref, EXT, k_w, nullptr, nullptr, B_K, NROWS_R, D, D);
    gram_kernel<<<NH, 256>>>();

    // --- x0 = xm * mask ---
    maskmul_kernel<<<(NROWS_M * D + 255) / 256, 256>>>(x);

    // --- 3 diffuser steps ---
    for (int step = 0; step < NSTEPS; step++) {
        bgemm_kernel<false, false><<<dim3(cdiv(2 * D, 128), cdiv(NROWS_M, 128)), 256>>>(
            nullptr, B_X, qv_w, nullptr, nullptr, B_QV, NROWS_M, 2 * D, D);
        qtv_wmat_kernel<<<8 * NH, 256>>>();
        qw_kernel<<<dim3(8 * NH, 7), 256>>>();
        bgemm_kernel<true, false><<<dim3(cdiv(D, 128), cdiv(NROWS_M, 128)), 256>>>(
            nullptr, B_Y, proj_w, proj_b, nullptr, B_Z, NROWS_M, D, D);
        ln_kernel<<<NROWS_M, 256>>>(ln_g, ln_b);
    }

    // --- final blend ---
    blend_kernel<<<(NROWS_M * D + 255) / 256, 256>>>(x, out);
}

// round 11
// speedup vs baseline: 2.2555x; 1.1057x over previous
#include <cuda_runtime.h>
#include <cuda_bf16.h>
#include <math.h>
#include <cstdint>

// ---------------------------------------------------------------------------
// TrustDiffuserModule — round 10: R7 (known pass, 1028us) + register-prefetch
// pipelining in the tensor-core GEMM. Nothing else changed.
//
// Math rewrite: mean_r (sQK_r^T)(sQK_r^T)^T V = Q * (s^2 * M * (Q^T V)),
// M = mean_r K_r^T K_r (64x64/head, once). Reference's (B,R,H,N,hd)->(B,R,N,C)
// reshape is a raw flatten (scrambled); reproduced by (B,H,N,hd) writes.
//
// GEMM precision: fp32 operands split as a = ah + al (bf16 each);
// C = Ah*Bh + Ah*Bl + Al*Bh accumulated in fp32 -> ~1e-5 relative error.
// ---------------------------------------------------------------------------

#define NROWS_M   1576
#define NROWS_ALL 3546
#define NROWS_R   1970
#define D         768
#define H1        192
#define H2        96
#define NH        12
#define HD        64
#define NSTEPS    3

constexpr size_t AL(size_t x) { return (x + 255) & ~size_t(255); }
constexpr size_t OFF_H    = 0;
constexpr size_t OFF_E    = OFF_H    + AL((size_t)NROWS_ALL * H1);
constexpr size_t OFF_MASK = OFF_E    + AL((size_t)NROWS_ALL * H2);
constexpr size_t OFF_K    = OFF_MASK + AL((size_t)NROWS_M);
constexpr size_t OFF_M    = OFF_K    + AL((size_t)NROWS_R * D);
constexpr size_t OFF_X    = OFF_M    + AL((size_t)NH * HD * HD);
constexpr size_t OFF_QV   = OFF_X    + AL((size_t)NROWS_M * D);
constexpr size_t OFF_W    = OFF_QV   + AL((size_t)NROWS_M * 2 * D);
constexpr size_t OFF_Y    = OFF_W    + AL((size_t)96 * HD * HD);
constexpr size_t OFF_Z    = OFF_Y    + AL((size_t)NROWS_M * D);
constexpr size_t SCRATCH  = OFF_Z    + AL((size_t)NROWS_M * D) + 128 * 2048;

__device__ float g_scratch[SCRATCH];

#define HBUF  (g_scratch + OFF_H)
#define EBUF  (g_scratch + OFF_E)
#define MASKB (g_scratch + OFF_MASK)
#define KBUF  (g_scratch + OFF_K)
#define MBUF  (g_scratch + OFF_M)
#define XCUR  (g_scratch + OFF_X)
#define QVBUF (g_scratch + OFF_QV)
#define WBUF  (g_scratch + OFF_W)
#define YBUF  (g_scratch + OFF_Y)
#define ZBUF  (g_scratch + OFF_Z)

enum Buf { EXT = 0, B_H, B_E, B_K, B_X, B_QV, B_Y, B_Z };
__device__ __forceinline__ float* bufPtr(int b, const float* ext) {
    switch (b) {
        case B_H:  return HBUF;
        case B_E:  return EBUF;
        case B_K:  return KBUF;
        case B_X:  return XCUR;
        case B_QV: return QVBUF;
        case B_Y:  return YBUF;
        case B_Z:  return ZBUF;
        default:   return (float*)ext;
    }
}

// ---------------------------------------------------------------------------
// Tensor-core GEMM, split-precision bf16.  C[M,N] = A[M,K] @ B[K,N]
// BM=128, BN=128, BK=32, 256 threads (8 warps as 2x4 -> 64x32 warp tiles).
// Register-prefetch pipelining: gmem loads for tile t+1 issue before the
// compute of tile t, hiding DRAM/L2 latency behind MMA work.
// Requires K % 32 == 0 (all call sites: 768 or 192).
// ---------------------------------------------------------------------------
__device__ __forceinline__ void cvt_split(float v, __nv_bfloat16& h, __nv_bfloat16& l) {
    h = __float2bfloat16(v);
    l = __float2bfloat16(v - __bfloat162float(h));
}
__device__ __forceinline__ uint32_t pack_bf2(__nv_bfloat16 x, __nv_bfloat16 y) {
    __nv_bfloat162 t;
    t.x = x; t.y = y;
    return *reinterpret_cast<uint32_t*>(&t);
}
__device__ __forceinline__ void mma_bf16(float* c, const uint32_t* a, const uint32_t* b) {
    asm volatile(
        "mma.sync.aligned.m16n8k16.row.col.f32.bf16.bf16.f32 "
        "{%0,%1,%2,%3}, {%4,%5,%6,%7}, {%8,%9}, {%0,%1,%2,%3};\n"
        : "+f"(c[0]), "+f"(c[1]), "+f"(c[2]), "+f"(c[3])
        : "r"(a[0]), "r"(a[1]), "r"(a[2]), "r"(a[3]), "r"(b[0]), "r"(b[1]));
}

template <bool BIAS, bool GELU>
__global__ __launch_bounds__(256)
void bgemm_kernel(const float* __restrict__ Aext, int Abuf,
                  const float* __restrict__ B,
                  const float* __restrict__ bias,
                  float* __restrict__ Cext, int Cbuf,
                  int M, int N, int K)
{
    constexpr int BM = 128, BN = 128, BK = 32;
    const float* A = bufPtr(Abuf, Aext);
    float* C = bufPtr(Cbuf, Cext);

    __shared__ __nv_bfloat16 Ah[BM][BK + 2], Al[BM][BK + 2];
    __shared__ __nv_bfloat16 Bh[BK][BN + 4], Bl[BK][BN + 4];

    const int tid  = threadIdx.x;
    const int wid  = tid >> 5;
    const int lane = tid & 31;
    const int g    = lane >> 2;       // 0..7
    const int t2   = (lane & 3) * 2;  // 0,2,4,6

    const int rowBase = blockIdx.y * BM;
    const int colBase = blockIdx.x * BN;
    const int warpRow = (wid >> 2) * 64;  // 0 or 64
    const int warpCol = (wid & 3) * 32;   // 0,32,64,96

    // stagers (same geometry as R7)
    const int ar  = tid >> 3;         // 0..31
    const int akc = (tid & 7) * 4;    // 0..28
    const int bkr = tid >> 5;         // 0..7
    const int bnc = (tid & 31) * 4;   // 0..124

    const bool fullN = (colBase + BN <= N);
    const int nt = K / BK;

    float c[4][4][4];
#pragma unroll
    for (int mi = 0; mi < 4; mi++)
#pragma unroll
        for (int ni = 0; ni < 4; ni++)
#pragma unroll
            for (int e = 0; e < 4; e++) c[mi][ni][e] = 0.f;

    float4 pa[4], pbv[4];

    auto loadT = [&](int t) {
        const int k0 = t * BK;
#pragma unroll
        for (int p = 0; p < 4; p++) {
            int r = p * 32 + ar;
            int gm = rowBase + r;
            pa[p] = make_float4(0.f, 0.f, 0.f, 0.f);
            if (gm < M) pa[p] = *(const float4*)&A[(size_t)gm * K + k0 + akc];
        }
#pragma unroll
        for (int p = 0; p < 4; p++) {
            int kr = p * 8 + bkr;
            if (fullN) {
                pbv[p] = *(const float4*)&B[(size_t)(k0 + kr) * N + colBase + bnc];
            } else {
                const float* brow = &B[(size_t)(k0 + kr) * N];
                float t0 = (colBase + bnc + 0 < N) ? brow[colBase + bnc + 0] : 0.f;
                float t1 = (colBase + bnc + 1 < N) ? brow[colBase + bnc + 1] : 0.f;
                float t2v = (colBase + bnc + 2 < N) ? brow[colBase + bnc + 2] : 0.f;
                float t3 = (colBase + bnc + 3 < N) ? brow[colBase + bnc + 3] : 0.f;
                pbv[p] = make_float4(t0, t1, t2v, t3);
            }
        }
    };
    auto storeT = [&]() {
#pragma unroll
        for (int p = 0; p < 4; p++) {
            int r = p * 32 + ar;
            __nv_bfloat16 h, l;
            cvt_split(pa[p].x, h, l); Ah[r][akc + 0] = h; Al[r][akc + 0] = l;
            cvt_split(pa[p].y, h, l); Ah[r][akc + 1] = h; Al[r][akc + 1] = l;
            cvt_split(pa[p].z, h, l); Ah[r][akc + 2] = h; Al[r][akc + 2] = l;
            cvt_split(pa[p].w, h, l); Ah[r][akc + 3] = h; Al[r][akc + 3] = l;
        }
#pragma unroll
        for (int p = 0; p < 4; p++) {
            int kr = p * 8 + bkr;
            __nv_bfloat16 h, l;
            cvt_split(pbv[p].x, h, l); Bh[kr][bnc + 0] = h; Bl[kr][bnc + 0] = l;
            cvt_split(pbv[p].y, h, l); Bh[kr][bnc + 1] = h; Bl[kr][bnc + 1] = l;
            cvt_split(pbv[p].z, h, l); Bh[kr][bnc + 2] = h; Bl[kr][bnc + 2] = l;
            cvt_split(pbv[p].w, h, l); Bh[kr][bnc + 3] = h; Bl[kr][bnc + 3] = l;
        }
    };

    loadT(0);

    for (int t = 0; t < nt; t++) {
        storeT();
        __syncthreads();
        if (t + 1 < nt) loadT(t + 1);   // overlap gmem latency with compute

        // --- compute: 2 k-steps of 16 ---
#pragma unroll
        for (int ks = 0; ks < BK; ks += 16) {
            uint32_t ahf[4][4], alf[4][4], bhf[4][2], blf[4][2];
#pragma unroll
            for (int mi = 0; mi < 4; mi++) {
                int r0 = warpRow + mi * 16 + g;
                int r1 = r0 + 8;
                ahf[mi][0] = *(const uint32_t*)&Ah[r0][ks + t2];
                ahf[mi][1] = *(const uint32_t*)&Ah[r1][ks + t2];
                ahf[mi][2] = *(const uint32_t*)&Ah[r0][ks + t2 + 8];
                ahf[mi][3] = *(const uint32_t*)&Ah[r1][ks + t2 + 8];
                alf[mi][0] = *(const uint32_t*)&Al[r0][ks + t2];
                alf[mi][1] = *(const uint32_t*)&Al[r1][ks + t2];
                alf[mi][2] = *(const uint32_t*)&Al[r0][ks + t2 + 8];
                alf[mi][3] = *(const uint32_t*)&Al[r1][ks + t2 + 8];
            }
#pragma unroll
            for (int ni = 0; ni < 4; ni++) {
                int n = warpCol + ni * 8 + g;
                bhf[ni][0] = pack_bf2(Bh[ks + t2][n],     Bh[ks + t2 + 1][n]);
                bhf[ni][1] = pack_bf2(Bh[ks + t2 + 8][n], Bh[ks + t2 + 9][n]);
                blf[ni][0] = pack_bf2(Bl[ks + t2][n],     Bl[ks + t2 + 1][n]);
                blf[ni][1] = pack_bf2(Bl[ks + t2 + 8][n], Bl[ks + t2 + 9][n]);
            }
#pragma unroll
            for (int mi = 0; mi < 4; mi++)
#pragma unroll
                for (int ni = 0; ni < 4; ni++) {
                    mma_bf16(c[mi][ni], ahf[mi], bhf[ni]);
                    mma_bf16(c[mi][ni], ahf[mi], blf[ni]);
                    mma_bf16(c[mi][ni], alf[mi], bhf[ni]);
                }
        }
        if (t + 1 < nt) __syncthreads();   // protect smem before next store
    }

    // --- epilogue ---
#pragma unroll
    for (int mi = 0; mi < 4; mi++) {
        int rm0 = rowBase + warpRow + mi * 16 + g;
        int rm1 = rm0 + 8;
#pragma unroll
        for (int ni = 0; ni < 4; ni++) {
            int cn = colBase + warpCol + ni * 8 + t2;
#pragma unroll
            for (int e = 0; e < 4; e++) {
                int gm = (e < 2) ? rm0 : rm1;
                int gn = cn + (e & 1);
                if (gm >= M || gn >= N) continue;
                float v = c[mi][ni][e];
                if (BIAS) v += bias[gn];
                if (GELU) v = 0.5f * v * (1.f + erff(v * 0.70710678118654752440f));
                C[(size_t)gm * N + gn] = v;
            }
        }
    }
}

__device__ __forceinline__ float warpSum(float v) {
#pragma unroll
    for (int o = 16; o; o >>= 1) v += __shfl_down_sync(0xffffffffu, v, o);
    return v;
}

// ---------------------------------------------------------------------------
// Projector mask
// ---------------------------------------------------------------------------
__global__ void mask_kernel()
{
    const float* E = EBUF;
    const int idx = blockIdx.x;
    const int n = idx % 197;
    const int lane = threadIdx.x;
    const float* ex = E + (size_t)idx * H2;

    float ex0 = ex[lane], ex1 = ex[lane + 32], ex2 = ex[lane + 64];
    float s = ex0 * ex0 + ex1 * ex1 + ex2 * ex2;
    s = warpSum(s);
    float nx = fmaxf(sqrtf(s), 1e-8f);
    nx = __shfl_sync(0xffffffffu, nx, 0);

    float csum = 0.f;
#pragma unroll
    for (int r = 0; r < 10; r++) {
        const float* er = E + (size_t)(NROWS_M + r * 197 + n) * H2;
        float e0 = er[lane], e1 = er[lane + 32], e2 = er[lane + 64];
        float d  = ex0 * e0 + ex1 * e1 + ex2 * e2;
        float n2 = e0 * e0 + e1 * e1 + e2 * e2;
        d  = warpSum(d);
        n2 = warpSum(n2);
        if (lane == 0) {
            float nr = fmaxf(sqrtf(n2), 1e-8f);
            csum += d / (nx * nr);
        }
    }
    if (lane == 0) {
        float c = (csum * 0.1f + 1.f) * 0.5f;
        MASKB[idx] = 0.5f + 0.5f * tanhf(25.f * (c - 0.5f));
    }
}

// ---------------------------------------------------------------------------
// Gram: M_h = (1/10) * sum_n K[n,h]^T K[n,h]
// ---------------------------------------------------------------------------
__global__ void gram_kernel()
{
    const float* Kb = KBUF;
    const int h = blockIdx.x;
    __shared__ float Ks[32][HD];
    const int tid = threadIdx.x;
    const int tj = tid % 16, ti = tid / 16;
    float acc[4][4] = {};

    for (int n0 = 0; n0 < NROWS_R; n0 += 32) {
        for (int i = tid; i < 32 * HD; i += 256) {
            int r = i / HD, c = i % HD;
            int n = n0 + r;
            Ks[r][c] = (n < NROWS_R) ? Kb[(size_t)n * D + h * HD + c] : 0.f;
        }
        __syncthreads();
#pragma unroll
        for (int r = 0; r < 32; r++) {
            float a[4], b[4];
#pragma unroll
            for (int i = 0; i < 4; i++) a[i] = Ks[r][ti * 4 + i];
#pragma unroll
            for (int j = 0; j < 4; j++) b[j] = Ks[r][tj * 4 + j];
#pragma unroll
            for (int i = 0; i < 4; i++)
#pragma unroll
                for (int j = 0; j < 4; j++) acc[i][j] += a[i] * b[j];
        }
        __syncthreads();
    }
#pragma unroll
    for (int i = 0; i < 4; i++)
#pragma unroll
        for (int j = 0; j < 4; j++)
            MBUF[(size_t)h * HD * HD + (ti * 4 + i) * HD + (tj * 4 + j)] = acc[i][j] * 0.1f;
}

// ---------------------------------------------------------------------------
// Fused qtv + wmat: P = Q^T V (inner 197); W = (1/64) * M_h @ P.
// ---------------------------------------------------------------------------
__global__ __launch_bounds__(256) void qtv_wmat_kernel()
{
    const float* QV = QVBUF;
    const int bh = blockIdx.x;
    const int b = bh / NH, h = bh % NH;
    __shared__ float Qs[32][HD];
    __shared__ float Vs[32][HD];
    __shared__ float Ps[HD][HD];
    __shared__ float Ms[HD][HD];
    const int tid = threadIdx.x;
    const int tj = tid % 16, ti = tid / 16;
    float acc[4][4] = {};

    for (int n0 = 0; n0 < 197; n0 += 32) {
        for (int i = tid; i < 32 * HD; i += 256) {
            int r = i / HD, c = i % HD;
            int n = n0 + r;
            float q = 0.f, v = 0.f;
            if (n < 197) {
                size_t base = (size_t)(b * 197 + n) * (2 * D) + h * HD + c;
                q = QV[base];
                v = QV[base + D];
            }
            Qs[r][c] = q;
            Vs[r][c] = v;
        }
        __syncthreads();
#pragma unroll
        for (int r = 0; r < 32; r++) {
            float a[4], bv[4];
#pragma unroll
            for (int i = 0; i < 4; i++) a[i] = Qs[r][ti * 4 + i];
#pragma unroll
            for (int j = 0; j < 4; j++) bv[j] = Vs[r][tj * 4 + j];
#pragma unroll
            for (int i = 0; i < 4; i++)
#pragma unroll
                for (int j = 0; j < 4; j++) acc[i][j] += a[i] * bv[j];
        }
        __syncthreads();
    }

#pragma unroll
    for (int i = 0; i < 4; i++)
#pragma unroll
        for (int j = 0; j < 4; j++)
            Ps[ti * 4 + i][tj * 4 + j] = acc[i][j];
    for (int i = tid; i < HD * HD; i += 256)
        Ms[i >> 6][i & 63] = MBUF[(size_t)h * HD * HD + i];
    __syncthreads();

    float w[4][4] = {};
#pragma unroll 8
    for (int k = 0; k < HD; k++) {
        float a[4], bv[4];
#pragma unroll
        for (int i = 0; i < 4; i++) a[i] = Ms[ti * 4 + i][k];
#pragma unroll
        for (int j = 0; j < 4; j++) bv[j] = Ps[k][tj * 4 + j];
#pragma unroll
        for (int i = 0; i < 4; i++)
#pragma unroll
            for (int j = 0; j < 4; j++) w[i][j] += a[i] * bv[j];
    }
#pragma unroll
    for (int i = 0; i < 4; i++)
#pragma unroll
        for (int j = 0; j < 4; j++)
            WBUF[(size_t)bh * HD * HD + (ti * 4 + i) * HD + (tj * 4 + j)] =
                w[i][j] * (1.f / 64.f);
}

// ---------------------------------------------------------------------------
// Y(b,h,n,:) = Q(b,h,n,:) @ W[b,h]; scrambled (B,H,N,hd) write.
// ---------------------------------------------------------------------------
__global__ void qw_kernel()
{
    const float* QV = QVBUF;
    const int bh = blockIdx.x;
    const int b = bh / NH, h = bh % NH;
    __shared__ float Ws[HD][HD];
    const int tid = threadIdx.x;
    for (int i = tid; i < HD * HD; i += 256)
        Ws[i / HD][i % HD] = WBUF[(size_t)bh * HD * HD + i];
    __syncthreads();

    const int lr = tid / 8;
    const int lc = (tid % 8) * 8;
    const int n = blockIdx.y * 32 + lr;
    if (n >= 197) return;

    const float* qrow = QV + (size_t)(b * 197 + n) * (2 * D) + h * HD;
    float acc[8] = {};
#pragma unroll 8
    for (int d = 0; d < HD; d++) {
        float q = qrow[d];
#pragma unroll
        for (int j = 0; j < 8; j++) acc[j] += q * Ws[d][lc + j];
    }
    float* yrow = YBUF + (size_t)b * (197 * D) + (size_t)h * (197 * HD)
                       + (size_t)n * HD + lc;
#pragma unroll
    for (int j = 0; j < 8; j++) yrow[j] = acc[j];
}

// ---------------------------------------------------------------------------
// LayerNorm (768). Z -> Xcur.
// ---------------------------------------------------------------------------
__global__ void ln_kernel(const float* __restrict__ g, const float* __restrict__ b)
{
    const int row = blockIdx.x;
    const float* z = ZBUF + (size_t)row * D;
    const int t = threadIdx.x;
    float v0 = z[t], v1 = z[t + 256], v2 = z[t + 512];
    float s = v0 + v1 + v2;
    float ss = v0 * v0 + v1 * v1 + v2 * v2;

    __shared__ float sh1[8], sh2[8];
    const int lane = t & 31, w = t >> 5;
    s = warpSum(s);
    ss = warpSum(ss);
    if (lane == 0) { sh1[w] = s; sh2[w] = ss; }
    __syncthreads();
    if (w == 0) {
        float a = lane < 8 ? sh1[lane] : 0.f;
        float c = lane < 8 ? sh2[lane] : 0.f;
        a = warpSum(a);
        c = warpSum(c);
        if (lane == 0) { sh1[0] = a; sh2[0] = c; }
    }
    __syncthreads();
    const float mu = sh1[0] * (1.f / 768.f);
    const float var = sh2[0] * (1.f / 768.f) - mu * mu;
    const float inv = rsqrtf(var + 1e-5f);
    float* o = XCUR + (size_t)row * D;
    o[t]       = (v0 - mu) * inv * g[t]       + b[t];
    o[t + 256] = (v1 - mu) * inv * g[t + 256] + b[t + 256];
    o[t + 512] = (v2 - mu) * inv * g[t + 512] + b[t + 512];
}

// ---------------------------------------------------------------------------
// Elementwise
// ---------------------------------------------------------------------------
__global__ void maskmul_kernel(const float* __restrict__ x)
{
    int i = blockIdx.x * blockDim.x + threadIdx.x;
    if (i < NROWS_M * D) XCUR[i] = x[i] * MASKB[i / D];
}

__global__ void blend_kernel(const float* __restrict__ x, float* __restrict__ out)
{
    int i = blockIdx.x * blockDim.x + threadIdx.x;
    if (i < NROWS_M * D) {
        float m = MASKB[i / D];
        out[i] = m * XCUR[i] + (1.f - m) * x[i];
    }
}

// ---------------------------------------------------------------------------
// Launch
// ---------------------------------------------------------------------------
extern "C" void kernel_launch(void* const* d_in, const int* in_sizes, int n_in,
                              void* d_out, int out_size)
{
    const float* x      = (const float*)d_in[0];
    const float* qv_w   = (const float*)d_in[1];
    const float* k_w    = (const float*)d_in[2];
    const float* proj_w = (const float*)d_in[3];
    const float* proj_b = (const float*)d_in[4];
    const float* ln_g   = (const float*)d_in[5];
    const float* ln_b   = (const float*)d_in[6];
    const float* fc1_w  = (const float*)d_in[7];
    const float* fc1_b  = (const float*)d_in[8];
    const float* fc2_w  = (const float*)d_in[9];
    const float* fc2_b  = (const float*)d_in[10];
    float* out = (float*)d_out;

    const float* ref = x + (size_t)NROWS_M * D;

    cudaMemcpyAsync(out + (size_t)NROWS_M * D, ref,
                    (size_t)NROWS_R * D * sizeof(float),
                    cudaMemcpyDeviceToDevice, 0);

    auto cdiv = [](int a, int b) { return (a + b - 1) / b; };

    // --- projector encoder ---
    bgemm_kernel<true, true><<<dim3(cdiv(H1, 128), cdiv(NROWS_ALL, 128)), 256>>>(
        x, EXT, fc1_w, fc1_b, nullptr, B_H, NROWS_ALL, H1, D);
    bgemm_kernel<true, false><<<dim3(cdiv(H2, 128), cdiv(NROWS_ALL, 128)), 256>>>(
        nullptr, B_H, fc2_w, fc2_b, nullptr, B_E, NROWS_ALL, H2, H1);
    mask_kernel<<<NROWS_M, 32>>>();

    // --- K projection + Gram ---
    bgemm_kernel<false, false><<<dim3(cdiv(D, 128), cdiv(NROWS_R, 128)), 256>>>(
        ref, EXT, k_w, nullptr, nullptr, B_K, NROWS_R, D, D);
    gram_kernel<<<NH, 256>>>();

    // --- x0 = xm * mask ---
    maskmul_kernel<<<(NROWS_M * D + 255) / 256, 256>>>(x);

    // --- 3 diffuser steps ---
    for (int step = 0; step < NSTEPS; step++) {
        bgemm_kernel<false, false><<<dim3(cdiv(2 * D, 128), cdiv(NROWS_M, 128)), 256>>>(
            nullptr, B_X, qv_w, nullptr, nullptr, B_QV, NROWS_M, 2 * D, D);
        qtv_wmat_kernel<<<8 * NH, 256>>>();
        qw_kernel<<<dim3(8 * NH, 7), 256>>>();
        bgemm_kernel<true, false><<<dim3(cdiv(D, 128), cdiv(NROWS_M, 128)), 256>>>(
            nullptr, B_Y, proj_w, proj_b, nullptr, B_Z, NROWS_M, D, D);
        ln_kernel<<<NROWS_M, 256>>>(ln_g, ln_b);
    }

    // --- final blend ---
    blend_kernel<<<(NROWS_M * D + 255) / 256, 256>>>(x, out);
}

// round 12
// speedup vs baseline: 2.3650x; 1.0486x over previous
#include <cuda_runtime.h>
#include <cuda_bf16.h>
#include <math.h>
#include <cstdint>

// ---------------------------------------------------------------------------
// TrustDiffuserModule — round 11: R10 (929us) with GEMM tile BN 128->64 so
// every GEMM grid covers all 148 SMs. Nothing else changed.
//
// Math rewrite: mean_r (sQK_r^T)(sQK_r^T)^T V = Q * (s^2 * M * (Q^T V)),
// M = mean_r K_r^T K_r (64x64/head, once). Reference's (B,R,H,N,hd)->(B,R,N,C)
// reshape is a raw flatten (scrambled); reproduced by (B,H,N,hd) writes.
//
// GEMM precision: fp32 operands split as a = ah + al (bf16 each);
// C = Ah*Bh + Ah*Bl + Al*Bh accumulated in fp32 -> ~1e-5 relative error.
// ---------------------------------------------------------------------------

#define NROWS_M   1576
#define NROWS_ALL 3546
#define NROWS_R   1970
#define D         768
#define H1        192
#define H2        96
#define NH        12
#define HD        64
#define NSTEPS    3

constexpr size_t AL(size_t x) { return (x + 255) & ~size_t(255); }
constexpr size_t OFF_H    = 0;
constexpr size_t OFF_E    = OFF_H    + AL((size_t)NROWS_ALL * H1);
constexpr size_t OFF_MASK = OFF_E    + AL((size_t)NROWS_ALL * H2);
constexpr size_t OFF_K    = OFF_MASK + AL((size_t)NROWS_M);
constexpr size_t OFF_M    = OFF_K    + AL((size_t)NROWS_R * D);
constexpr size_t OFF_X    = OFF_M    + AL((size_t)NH * HD * HD);
constexpr size_t OFF_QV   = OFF_X    + AL((size_t)NROWS_M * D);
constexpr size_t OFF_W    = OFF_QV   + AL((size_t)NROWS_M * 2 * D);
constexpr size_t OFF_Y    = OFF_W    + AL((size_t)96 * HD * HD);
constexpr size_t OFF_Z    = OFF_Y    + AL((size_t)NROWS_M * D);
constexpr size_t SCRATCH  = OFF_Z    + AL((size_t)NROWS_M * D) + 128 * 2048;

__device__ float g_scratch[SCRATCH];

#define HBUF  (g_scratch + OFF_H)
#define EBUF  (g_scratch + OFF_E)
#define MASKB (g_scratch + OFF_MASK)
#define KBUF  (g_scratch + OFF_K)
#define MBUF  (g_scratch + OFF_M)
#define XCUR  (g_scratch + OFF_X)
#define QVBUF (g_scratch + OFF_QV)
#define WBUF  (g_scratch + OFF_W)
#define YBUF  (g_scratch + OFF_Y)
#define ZBUF  (g_scratch + OFF_Z)

enum Buf { EXT = 0, B_H, B_E, B_K, B_X, B_QV, B_Y, B_Z };
__device__ __forceinline__ float* bufPtr(int b, const float* ext) {
    switch (b) {
        case B_H:  return HBUF;
        case B_E:  return EBUF;
        case B_K:  return KBUF;
        case B_X:  return XCUR;
        case B_QV: return QVBUF;
        case B_Y:  return YBUF;
        case B_Z:  return ZBUF;
        default:   return (float*)ext;
    }
}

// ---------------------------------------------------------------------------
// Tensor-core GEMM, split-precision bf16.  C[M,N] = A[M,K] @ B[K,N]
// BM=128, BN=64, BK=32, 256 threads (8 warps as 4x2 -> 32x32 warp tiles).
// Register-prefetch pipelining (gmem loads for tile t+1 overlap compute of t).
// Requires K % 32 == 0 (all call sites: 768 or 192).
// ---------------------------------------------------------------------------
__device__ __forceinline__ void cvt_split(float v, __nv_bfloat16& h, __nv_bfloat16& l) {
    h = __float2bfloat16(v);
    l = __float2bfloat16(v - __bfloat162float(h));
}
__device__ __forceinline__ uint32_t pack_bf2(__nv_bfloat16 x, __nv_bfloat16 y) {
    __nv_bfloat162 t;
    t.x = x; t.y = y;
    return *reinterpret_cast<uint32_t*>(&t);
}
__device__ __forceinline__ void mma_bf16(float* c, const uint32_t* a, const uint32_t* b) {
    asm volatile(
        "mma.sync.aligned.m16n8k16.row.col.f32.bf16.bf16.f32 "
        "{%0,%1,%2,%3}, {%4,%5,%6,%7}, {%8,%9}, {%0,%1,%2,%3};\n"
        : "+f"(c[0]), "+f"(c[1]), "+f"(c[2]), "+f"(c[3])
        : "r"(a[0]), "r"(a[1]), "r"(a[2]), "r"(a[3]), "r"(b[0]), "r"(b[1]));
}

template <bool BIAS, bool GELU>
__global__ __launch_bounds__(256)
void bgemm_kernel(const float* __restrict__ Aext, int Abuf,
                  const float* __restrict__ B,
                  const float* __restrict__ bias,
                  float* __restrict__ Cext, int Cbuf,
                  int M, int N, int K)
{
    constexpr int BM = 128, BN = 64, BK = 32;
    const float* A = bufPtr(Abuf, Aext);
    float* C = bufPtr(Cbuf, Cext);

    __shared__ __nv_bfloat16 Ah[BM][BK + 2], Al[BM][BK + 2];
    __shared__ __nv_bfloat16 Bh[BK][BN + 4], Bl[BK][BN + 4];

    const int tid  = threadIdx.x;
    const int wid  = tid >> 5;
    const int lane = tid & 31;
    const int g    = lane >> 2;       // 0..7
    const int t2   = (lane & 3) * 2;  // 0,2,4,6

    const int rowBase = blockIdx.y * BM;
    const int colBase = blockIdx.x * BN;
    const int warpRow = (wid >> 1) * 32;  // 0,32,64,96
    const int warpCol = (wid & 1) * 32;   // 0,32

    // stagers
    const int ar  = tid >> 3;         // 0..31
    const int akc = (tid & 7) * 4;    // 0..28
    const int bkr = tid >> 4;         // 0..15
    const int bnc = (tid & 15) * 4;   // 0..60

    const bool fullN = (colBase + BN <= N);
    const int nt = K / BK;

    float c[2][4][4];
#pragma unroll
    for (int mi = 0; mi < 2; mi++)
#pragma unroll
        for (int ni = 0; ni < 4; ni++)
#pragma unroll
            for (int e = 0; e < 4; e++) c[mi][ni][e] = 0.f;

    float4 pa[4], pbv[2];

    auto loadT = [&](int t) {
        const int k0 = t * BK;
#pragma unroll
        for (int p = 0; p < 4; p++) {
            int r = p * 32 + ar;
            int gm = rowBase + r;
            pa[p] = make_float4(0.f, 0.f, 0.f, 0.f);
            if (gm < M) pa[p] = *(const float4*)&A[(size_t)gm * K + k0 + akc];
        }
#pragma unroll
        for (int p = 0; p < 2; p++) {
            int kr = p * 16 + bkr;
            if (fullN) {
                pbv[p] = *(const float4*)&B[(size_t)(k0 + kr) * N + colBase + bnc];
            } else {
                const float* brow = &B[(size_t)(k0 + kr) * N];
                float t0 = (colBase + bnc + 0 < N) ? brow[colBase + bnc + 0] : 0.f;
                float t1 = (colBase + bnc + 1 < N) ? brow[colBase + bnc + 1] : 0.f;
                float t2v = (colBase + bnc + 2 < N) ? brow[colBase + bnc + 2] : 0.f;
                float t3 = (colBase + bnc + 3 < N) ? brow[colBase + bnc + 3] : 0.f;
                pbv[p] = make_float4(t0, t1, t2v, t3);
            }
        }
    };
    auto storeT = [&]() {
#pragma unroll
        for (int p = 0; p < 4; p++) {
            int r = p * 32 + ar;
            __nv_bfloat16 h, l;
            cvt_split(pa[p].x, h, l); Ah[r][akc + 0] = h; Al[r][akc + 0] = l;
            cvt_split(pa[p].y, h, l); Ah[r][akc + 1] = h; Al[r][akc + 1] = l;
            cvt_split(pa[p].z, h, l); Ah[r][akc + 2] = h; Al[r][akc + 2] = l;
            cvt_split(pa[p].w, h, l); Ah[r][akc + 3] = h; Al[r][akc + 3] = l;
        }
#pragma unroll
        for (int p = 0; p < 2; p++) {
            int kr = p * 16 + bkr;
            __nv_bfloat16 h, l;
            cvt_split(pbv[p].x, h, l); Bh[kr][bnc + 0] = h; Bl[kr][bnc + 0] = l;
            cvt_split(pbv[p].y, h, l); Bh[kr][bnc + 1] = h; Bl[kr][bnc + 1] = l;
            cvt_split(pbv[p].z, h, l); Bh[kr][bnc + 2] = h; Bl[kr][bnc + 2] = l;
            cvt_split(pbv[p].w, h, l); Bh[kr][bnc + 3] = h; Bl[kr][bnc + 3] = l;
        }
    };

    loadT(0);

    for (int t = 0; t < nt; t++) {
        storeT();
        __syncthreads();
        if (t + 1 < nt) loadT(t + 1);   // overlap gmem latency with compute

        // --- compute: 2 k-steps of 16 ---
#pragma unroll
        for (int ks = 0; ks < BK; ks += 16) {
            uint32_t ahf[2][4], alf[2][4], bhf[4][2], blf[4][2];
#pragma unroll
            for (int mi = 0; mi < 2; mi++) {
                int r0 = warpRow + mi * 16 + g;
                int r1 = r0 + 8;
                ahf[mi][0] = *(const uint32_t*)&Ah[r0][ks + t2];
                ahf[mi][1] = *(const uint32_t*)&Ah[r1][ks + t2];
                ahf[mi][2] = *(const uint32_t*)&Ah[r0][ks + t2 + 8];
                ahf[mi][3] = *(const uint32_t*)&Ah[r1][ks + t2 + 8];
                alf[mi][0] = *(const uint32_t*)&Al[r0][ks + t2];
                alf[mi][1] = *(const uint32_t*)&Al[r1][ks + t2];
                alf[mi][2] = *(const uint32_t*)&Al[r0][ks + t2 + 8];
                alf[mi][3] = *(const uint32_t*)&Al[r1][ks + t2 + 8];
            }
#pragma unroll
            for (int ni = 0; ni < 4; ni++) {
                int n = warpCol + ni * 8 + g;
                bhf[ni][0] = pack_bf2(Bh[ks + t2][n],     Bh[ks + t2 + 1][n]);
                bhf[ni][1] = pack_bf2(Bh[ks + t2 + 8][n], Bh[ks + t2 + 9][n]);
                blf[ni][0] = pack_bf2(Bl[ks + t2][n],     Bl[ks + t2 + 1][n]);
                blf[ni][1] = pack_bf2(Bl[ks + t2 + 8][n], Bl[ks + t2 + 9][n]);
            }
#pragma unroll
            for (int mi = 0; mi < 2; mi++)
#pragma unroll
                for (int ni = 0; ni < 4; ni++) {
                    mma_bf16(c[mi][ni], ahf[mi], bhf[ni]);
                    mma_bf16(c[mi][ni], ahf[mi], blf[ni]);
                    mma_bf16(c[mi][ni], alf[mi], bhf[ni]);
                }
        }
        if (t + 1 < nt) __syncthreads();   // protect smem before next store
    }

    // --- epilogue ---
#pragma unroll
    for (int mi = 0; mi < 2; mi++) {
        int rm0 = rowBase + warpRow + mi * 16 + g;
        int rm1 = rm0 + 8;
#pragma unroll
        for (int ni = 0; ni < 4; ni++) {
            int cn = colBase + warpCol + ni * 8 + t2;
#pragma unroll
            for (int e = 0; e < 4; e++) {
                int gm = (e < 2) ? rm0 : rm1;
                int gn = cn + (e & 1);
                if (gm >= M || gn >= N) continue;
                float v = c[mi][ni][e];
                if (BIAS) v += bias[gn];
                if (GELU) v = 0.5f * v * (1.f + erff(v * 0.70710678118654752440f));
                C[(size_t)gm * N + gn] = v;
            }
        }
    }
}

__device__ __forceinline__ float warpSum(float v) {
#pragma unroll
    for (int o = 16; o; o >>= 1) v += __shfl_down_sync(0xffffffffu, v, o);
    return v;
}

// ---------------------------------------------------------------------------
// Projector mask
// ---------------------------------------------------------------------------
__global__ void mask_kernel()
{
    const float* E = EBUF;
    const int idx = blockIdx.x;
    const int n = idx % 197;
    const int lane = threadIdx.x;
    const float* ex = E + (size_t)idx * H2;

    float ex0 = ex[lane], ex1 = ex[lane + 32], ex2 = ex[lane + 64];
    float s = ex0 * ex0 + ex1 * ex1 + ex2 * ex2;
    s = warpSum(s);
    float nx = fmaxf(sqrtf(s), 1e-8f);
    nx = __shfl_sync(0xffffffffu, nx, 0);

    float csum = 0.f;
#pragma unroll
    for (int r = 0; r < 10; r++) {
        const float* er = E + (size_t)(NROWS_M + r * 197 + n) * H2;
        float e0 = er[lane], e1 = er[lane + 32], e2 = er[lane + 64];
        float d  = ex0 * e0 + ex1 * e1 + ex2 * e2;
        float n2 = e0 * e0 + e1 * e1 + e2 * e2;
        d  = warpSum(d);
        n2 = warpSum(n2);
        if (lane == 0) {
            float nr = fmaxf(sqrtf(n2), 1e-8f);
            csum += d / (nx * nr);
        }
    }
    if (lane == 0) {
        float c = (csum * 0.1f + 1.f) * 0.5f;
        MASKB[idx] = 0.5f + 0.5f * tanhf(25.f * (c - 0.5f));
    }
}

// ---------------------------------------------------------------------------
// Gram: M_h = (1/10) * sum_n K[n,h]^T K[n,h]
// ---------------------------------------------------------------------------
__global__ void gram_kernel()
{
    const float* Kb = KBUF;
    const int h = blockIdx.x;
    __shared__ float Ks[32][HD];
    const int tid = threadIdx.x;
    const int tj = tid % 16, ti = tid / 16;
    float acc[4][4] = {};

    for (int n0 = 0; n0 < NROWS_R; n0 += 32) {
        for (int i = tid; i < 32 * HD; i += 256) {
            int r = i / HD, c = i % HD;
            int n = n0 + r;
            Ks[r][c] = (n < NROWS_R) ? Kb[(size_t)n * D + h * HD + c] : 0.f;
        }
        __syncthreads();
#pragma unroll
        for (int r = 0; r < 32; r++) {
            float a[4], b[4];
#pragma unroll
            for (int i = 0; i < 4; i++) a[i] = Ks[r][ti * 4 + i];
#pragma unroll
            for (int j = 0; j < 4; j++) b[j] = Ks[r][tj * 4 + j];
#pragma unroll
            for (int i = 0; i < 4; i++)
#pragma unroll
                for (int j = 0; j < 4; j++) acc[i][j] += a[i] * b[j];
        }
        __syncthreads();
    }
#pragma unroll
    for (int i = 0; i < 4; i++)
#pragma unroll
        for (int j = 0; j < 4; j++)
            MBUF[(size_t)h * HD * HD + (ti * 4 + i) * HD + (tj * 4 + j)] = acc[i][j] * 0.1f;
}

// ---------------------------------------------------------------------------
// Fused qtv + wmat: P = Q^T V (inner 197); W = (1/64) * M_h @ P.
// ---------------------------------------------------------------------------
__global__ __launch_bounds__(256) void qtv_wmat_kernel()
{
    const float* QV = QVBUF;
    const int bh = blockIdx.x;
    const int b = bh / NH, h = bh % NH;
    __shared__ float Qs[32][HD];
    __shared__ float Vs[32][HD];
    __shared__ float Ps[HD][HD];
    __shared__ float Ms[HD][HD];
    const int tid = threadIdx.x;
    const int tj = tid % 16, ti = tid / 16;
    float acc[4][4] = {};

    for (int n0 = 0; n0 < 197; n0 += 32) {
        for (int i = tid; i < 32 * HD; i += 256) {
            int r = i / HD, c = i % HD;
            int n = n0 + r;
            float q = 0.f, v = 0.f;
            if (n < 197) {
                size_t base = (size_t)(b * 197 + n) * (2 * D) + h * HD + c;
                q = QV[base];
                v = QV[base + D];
            }
            Qs[r][c] = q;
            Vs[r][c] = v;
        }
        __syncthreads();
#pragma unroll
        for (int r = 0; r < 32; r++) {
            float a[4], bv[4];
#pragma unroll
            for (int i = 0; i < 4; i++) a[i] = Qs[r][ti * 4 + i];
#pragma unroll
            for (int j = 0; j < 4; j++) bv[j] = Vs[r][tj * 4 + j];
#pragma unroll
            for (int i = 0; i < 4; i++)
#pragma unroll
                for (int j = 0; j < 4; j++) acc[i][j] += a[i] * bv[j];
        }
        __syncthreads();
    }

#pragma unroll
    for (int i = 0; i < 4; i++)
#pragma unroll
        for (int j = 0; j < 4; j++)
            Ps[ti * 4 + i][tj * 4 + j] = acc[i][j];
    for (int i = tid; i < HD * HD; i += 256)
        Ms[i >> 6][i & 63] = MBUF[(size_t)h * HD * HD + i];
    __syncthreads();

    float w[4][4] = {};
#pragma unroll 8
    for (int k = 0; k < HD; k++) {
        float a[4], bv[4];
#pragma unroll
        for (int i = 0; i < 4; i++) a[i] = Ms[ti * 4 + i][k];
#pragma unroll
        for (int j = 0; j < 4; j++) bv[j] = Ps[k][tj * 4 + j];
#pragma unroll
        for (int i = 0; i < 4; i++)
#pragma unroll
            for (int j = 0; j < 4; j++) w[i][j] += a[i] * bv[j];
    }
#pragma unroll
    for (int i = 0; i < 4; i++)
#pragma unroll
        for (int j = 0; j < 4; j++)
            WBUF[(size_t)bh * HD * HD + (ti * 4 + i) * HD + (tj * 4 + j)] =
                w[i][j] * (1.f / 64.f);
}

// ---------------------------------------------------------------------------
// Y(b,h,n,:) = Q(b,h,n,:) @ W[b,h]; scrambled (B,H,N,hd) write.
// ---------------------------------------------------------------------------
__global__ void qw_kernel()
{
    const float* QV = QVBUF;
    const int bh = blockIdx.x;
    const int b = bh / NH, h = bh % NH;
    __shared__ float Ws[HD][HD];
    const int tid = threadIdx.x;
    for (int i = tid; i < HD * HD; i += 256)
        Ws[i / HD][i % HD] = WBUF[(size_t)bh * HD * HD + i];
    __syncthreads();

    const int lr = tid / 8;
    const int lc = (tid % 8) * 8;
    const int n = blockIdx.y * 32 + lr;
    if (n >= 197) return;

    const float* qrow = QV + (size_t)(b * 197 + n) * (2 * D) + h * HD;
    float acc[8] = {};
#pragma unroll 8
    for (int d = 0; d < HD; d++) {
        float q = qrow[d];
#pragma unroll
        for (int j = 0; j < 8; j++) acc[j] += q * Ws[d][lc + j];
    }
    float* yrow = YBUF + (size_t)b * (197 * D) + (size_t)h * (197 * HD)
                       + (size_t)n * HD + lc;
#pragma unroll
    for (int j = 0; j < 8; j++) yrow[j] = acc[j];
}

// ---------------------------------------------------------------------------
// LayerNorm (768). Z -> Xcur.
// ---------------------------------------------------------------------------
__global__ void ln_kernel(const float* __restrict__ g, const float* __restrict__ b)
{
    const int row = blockIdx.x;
    const float* z = ZBUF + (size_t)row * D;
    const int t = threadIdx.x;
    float v0 = z[t], v1 = z[t + 256], v2 = z[t + 512];
    float s = v0 + v1 + v2;
    float ss = v0 * v0 + v1 * v1 + v2 * v2;

    __shared__ float sh1[8], sh2[8];
    const int lane = t & 31, w = t >> 5;
    s = warpSum(s);
    ss = warpSum(ss);
    if (lane == 0) { sh1[w] = s; sh2[w] = ss; }
    __syncthreads();
    if (w == 0) {
        float a = lane < 8 ? sh1[lane] : 0.f;
        float c = lane < 8 ? sh2[lane] : 0.f;
        a = warpSum(a);
        c = warpSum(c);
        if (lane == 0) { sh1[0] = a; sh2[0] = c; }
    }
    __syncthreads();
    const float mu = sh1[0] * (1.f / 768.f);
    const float var = sh2[0] * (1.f / 768.f) - mu * mu;
    const float inv = rsqrtf(var + 1e-5f);
    float* o = XCUR + (size_t)row * D;
    o[t]       = (v0 - mu) * inv * g[t]       + b[t];
    o[t + 256] = (v1 - mu) * inv * g[t + 256] + b[t + 256];
    o[t + 512] = (v2 - mu) * inv * g[t + 512] + b[t + 512];
}

// ---------------------------------------------------------------------------
// Elementwise
// ---------------------------------------------------------------------------
__global__ void maskmul_kernel(const float* __restrict__ x)
{
    int i = blockIdx.x * blockDim.x + threadIdx.x;
    if (i < NROWS_M * D) XCUR[i] = x[i] * MASKB[i / D];
}

__global__ void blend_kernel(const float* __restrict__ x, float* __restrict__ out)
{
    int i = blockIdx.x * blockDim.x + threadIdx.x;
    if (i < NROWS_M * D) {
        float m = MASKB[i / D];
        out[i] = m * XCUR[i] + (1.f - m) * x[i];
    }
}

// ---------------------------------------------------------------------------
// Launch
// ---------------------------------------------------------------------------
extern "C" void kernel_launch(void* const* d_in, const int* in_sizes, int n_in,
                              void* d_out, int out_size)
{
    const float* x      = (const float*)d_in[0];
    const float* qv_w   = (const float*)d_in[1];
    const float* k_w    = (const float*)d_in[2];
    const float* proj_w = (const float*)d_in[3];
    const float* proj_b = (const float*)d_in[4];
    const float* ln_g   = (const float*)d_in[5];
    const float* ln_b   = (const float*)d_in[6];
    const float* fc1_w  = (const float*)d_in[7];
    const float* fc1_b  = (const float*)d_in[8];
    const float* fc2_w  = (const float*)d_in[9];
    const float* fc2_b  = (const float*)d_in[10];
    float* out = (float*)d_out;

    const float* ref = x + (size_t)NROWS_M * D;

    cudaMemcpyAsync(out + (size_t)NROWS_M * D, ref,
                    (size_t)NROWS_R * D * sizeof(float),
                    cudaMemcpyDeviceToDevice, 0);

    auto cdiv = [](int a, int b) { return (a + b - 1) / b; };

    // --- projector encoder ---
    bgemm_kernel<true, true><<<dim3(cdiv(H1, 64), cdiv(NROWS_ALL, 128)), 256>>>(
        x, EXT, fc1_w, fc1_b, nullptr, B_H, NROWS_ALL, H1, D);
    bgemm_kernel<true, false><<<dim3(cdiv(H2, 64), cdiv(NROWS_ALL, 128)), 256>>>(
        nullptr, B_H, fc2_w, fc2_b, nullptr, B_E, NROWS_ALL, H2, H1);
    mask_kernel<<<NROWS_M, 32>>>();

    // --- K projection + Gram ---
    bgemm_kernel<false, false><<<dim3(cdiv(D, 64), cdiv(NROWS_R, 128)), 256>>>(
        ref, EXT, k_w, nullptr, nullptr, B_K, NROWS_R, D, D);
    gram_kernel<<<NH, 256>>>();

    // --- x0 = xm * mask ---
    maskmul_kernel<<<(NROWS_M * D + 255) / 256, 256>>>(x);

    // --- 3 diffuser steps ---
    for (int step = 0; step < NSTEPS; step++) {
        bgemm_kernel<false, false><<<dim3(cdiv(2 * D, 64), cdiv(NROWS_M, 128)), 256>>>(
            nullptr, B_X, qv_w, nullptr, nullptr, B_QV, NROWS_M, 2 * D, D);
        qtv_wmat_kernel<<<8 * NH, 256>>>();
        qw_kernel<<<dim3(8 * NH, 7), 256>>>();
        bgemm_kernel<true, false><<<dim3(cdiv(D, 64), cdiv(NROWS_M, 128)), 256>>>(
            nullptr, B_Y, proj_w, proj_b, nullptr, B_Z, NROWS_M, D, D);
        ln_kernel<<<NROWS_M, 256>>>(ln_g, ln_b);
    }

    // --- final blend ---
    blend_kernel<<<(NROWS_M * D + 255) / 256, 256>>>(x, out);
}

// round 14
// speedup vs baseline: 2.6737x; 1.1305x over previous
#include <cuda_runtime.h>
#include <cuda_bf16.h>
#include <math.h>
#include <cstdint>

// ---------------------------------------------------------------------------
// TrustDiffuserModule — round 12: hoisted bf16 hi/lo operand conversion
// (weights transposed+split once; activations split by producers), GEMM loop
// reduced to pure load/store/MMA. Single g_scratch arena, 35.2MB (< proven
// 37.3MB static budget), aggressive liveness-checked aliasing. No cp.async.
//
// Math rewrite: mean_r (sQK_r^T)(sQK_r^T)^T V = Q * (s^2 * M * (Q^T V)),
// M = mean_r K_r^T K_r (64x64/head, once). Reference's (B,R,H,N,hd)->(B,R,N,C)
// reshape is a raw flatten (scrambled); reproduced by (B,H,N,hd) writes.
//
// GEMM precision: fp32 = hi + lo (bf16 each); C = Ah*Bh + Ah*Bl + Al*Bh.
// ---------------------------------------------------------------------------

#define NROWS_M   1576
#define NROWS_ALL 3546
#define NROWS_R   1970
#define D         768
#define H1        192
#define H2        96
#define NH        12
#define HD        64
#define NSTEPS    3

// ---- arena offsets (float units; all even; liveness documented) ----
constexpr size_t F_WQV = 0;        // wqv hi+lo  (2*D*2D bf16 = 1,179,648 fl)
constexpr size_t F_WP  = 1179648;  // wp hi+lo   (589,824 fl)
constexpr size_t F_WK  = 1769472;  // wk hi+lo   (589,824 fl)   dead after kproj
constexpr size_t F_WF1 = 2359296;  // wf1 hi+lo  (147,456 fl)   dead after fc1
constexpr size_t F_WF2 = 2506752;  // wf2 hi+lo  (18,432 fl)    dead after fc2
constexpr size_t F_HB  = 2525184;  // H hi+lo    (680,832 fl)   dead after fc2
constexpr size_t F_Z   = F_WK;     // Z fp32 (1,210,368 fl) aliases wk..H (all dead in steps)
constexpr size_t F_XA  = 3206016;  // x arena (2,723,328 fl)
constexpr size_t F_XH  = F_XA;     //   x_hi (2,723,328 bf16); dead after kproj
constexpr size_t F_XL  = 4567680;  //   x_lo
constexpr size_t F_XCH = 3206016;  //   XC hi (1,210,368 bf16 = 605,184 fl) after kproj
constexpr size_t F_XCL = 3811200;  //   XC lo
constexpr size_t F_YH  = 4416384;  //   Y hi
constexpr size_t F_YL  = 5021568;  //   Y lo  (ends 5,626,752 <= arena end 5,929,344)
constexpr size_t F_MASK= 5929344;  // 2,048 fl
constexpr size_t F_M   = 5931392;  // 49,152 fl
constexpr size_t F_W   = 5980544;  // 393,216 fl
constexpr size_t F_QV  = 6373760;  // QV fp32 (2,420,736 fl)
constexpr size_t F_E   = F_QV;     //   E fp32 (340,416 fl) dead before step 1
constexpr size_t F_K   = 6714368;  //   K fp32 (1,512,960 fl) dead before step 1
constexpr size_t F_TOTAL = 8794496;  // 35.2 MB

__device__ float g_scratch[F_TOTAL];

#define BF16P(off) ((__nv_bfloat16*)(g_scratch + (off)))
#define MASKB (g_scratch + F_MASK)
#define KBUF  (g_scratch + F_K)
#define MBUF  (g_scratch + F_M)
#define QVBUF (g_scratch + F_QV)
#define EBUF  (g_scratch + F_E)
#define WBUF  (g_scratch + F_W)
#define ZBUF  (g_scratch + F_Z)

enum ASel { A_X = 0, A_XREF, A_H, A_XC, A_Y };
enum BSel { BW_QV = 0, BW_K, BW_P, BW_F1, BW_F2 };
enum CSel { C_K = 0, C_QV, C_Z, C_E };

__device__ __forceinline__ void aptr(int s, const __nv_bfloat16*& h, const __nv_bfloat16*& l) {
    switch (s) {
        case A_X:    h = BF16P(F_XH); l = BF16P(F_XL); break;
        case A_XREF: h = BF16P(F_XH) + (size_t)NROWS_M * D;
                     l = BF16P(F_XL) + (size_t)NROWS_M * D; break;
        case A_H:    h = BF16P(F_HB); l = BF16P(F_HB) + (size_t)NROWS_ALL * H1; break;
        case A_XC:   h = BF16P(F_XCH); l = BF16P(F_XCL); break;
        default:     h = BF16P(F_YH);  l = BF16P(F_YL);  break;
    }
}
__device__ __forceinline__ void bptr(int s, const __nv_bfloat16*& h, const __nv_bfloat16*& l) {
    switch (s) {
        case BW_QV: h = BF16P(F_WQV); l = BF16P(F_WQV) + (size_t)2 * D * D; break;
        case BW_K:  h = BF16P(F_WK);  l = BF16P(F_WK)  + (size_t)D * D;     break;
        case BW_P:  h = BF16P(F_WP);  l = BF16P(F_WP)  + (size_t)D * D;     break;
        case BW_F1: h = BF16P(F_WF1); l = BF16P(F_WF1) + (size_t)H1 * D;    break;
        default:    h = BF16P(F_WF2); l = BF16P(F_WF2) + (size_t)H2 * H1;   break;
    }
}
__device__ __forceinline__ float* cptr(int s) {
    switch (s) {
        case C_K:  return KBUF;
        case C_QV: return QVBUF;
        case C_Z:  return ZBUF;
        default:   return EBUF;
    }
}

__device__ __forceinline__ void split_bf(float v, __nv_bfloat16& h, __nv_bfloat16& l) {
    h = __float2bfloat16(v);
    l = __float2bfloat16(v - __bfloat162float(h));
}
__device__ __forceinline__ void mma_bf16(float* c, const uint32_t* a, const uint32_t* b) {
    asm volatile(
        "mma.sync.aligned.m16n8k16.row.col.f32.bf16.bf16.f32 "
        "{%0,%1,%2,%3}, {%4,%5,%6,%7}, {%8,%9}, {%0,%1,%2,%3};\n"
        : "+f"(c[0]), "+f"(c[1]), "+f"(c[2]), "+f"(c[3])
        : "r"(a[0]), "r"(a[1]), "r"(a[2]), "r"(a[3]), "r"(b[0]), "r"(b[1]));
}

// ---------------------------------------------------------------------------
// Tensor-core GEMM: C[M,N] = A[M,K] @ Bt[N,K]^T, pre-split bf16 hi/lo.
// BM=128, BN=64, BK=32, 256 threads (8 warps as 4x2 -> 32x32 warp tiles).
// Register-prefetch pipelining. K % 32 == 0 at all call sites.
// HILO: epilogue writes hi/lo bf16 into the H arena instead of fp32 C.
// ---------------------------------------------------------------------------
template <bool BIAS, bool GELU, bool HILO>
__global__ __launch_bounds__(256)
void bgemm_kernel(int asel, int bsel, const float* __restrict__ bias,
                  int csel, int M, int N, int K)
{
    constexpr int BM = 128, BN = 64, BK = 32;
    const __nv_bfloat16 *Ahg, *Alg, *Bhg, *Blg;
    aptr(asel, Ahg, Alg);
    bptr(bsel, Bhg, Blg);
    float* C = cptr(csel);
    __nv_bfloat16* Chh = BF16P(F_HB);
    __nv_bfloat16* Chl = BF16P(F_HB) + (size_t)NROWS_ALL * H1;

    __shared__ __nv_bfloat16 Ah[BM][BK + 8], Al[BM][BK + 8];
    __shared__ __nv_bfloat16 Bh[BN][BK + 8], Bl[BN][BK + 8];

    const int tid  = threadIdx.x;
    const int wid  = tid >> 5;
    const int lane = tid & 31;
    const int g    = lane >> 2;       // 0..7
    const int t2   = (lane & 3) * 2;  // 0,2,4,6

    const int rowBase = blockIdx.y * BM;
    const int colBase = blockIdx.x * BN;
    const int warpRow = (wid >> 1) * 32;  // 0,32,64,96
    const int warpCol = (wid & 1) * 32;   // 0,32

    // stagers: uint4 = 8 bf16
    const int ar = tid >> 2;          // 0..63 (rows ar and ar+64)
    const int ac = (tid & 3) * 8;     // 0,8,16,24
    const int bn = tid >> 2;          // 0..63
    const int bc = (tid & 3) * 8;

    const int nt = K / BK;

    float c[2][4][4];
#pragma unroll
    for (int mi = 0; mi < 2; mi++)
#pragma unroll
        for (int ni = 0; ni < 4; ni++)
#pragma unroll
            for (int e = 0; e < 4; e++) c[mi][ni][e] = 0.f;

    uint4 pah[2], pal[2], pbh, pbl;
    const uint4 z4 = make_uint4(0u, 0u, 0u, 0u);

    auto loadT = [&](int t) {
        const int k0 = t * BK;
#pragma unroll
        for (int p = 0; p < 2; p++) {
            int gm = rowBase + ar + p * 64;
            pah[p] = z4; pal[p] = z4;
            if (gm < M) {
                pah[p] = *(const uint4*)&Ahg[(size_t)gm * K + k0 + ac];
                pal[p] = *(const uint4*)&Alg[(size_t)gm * K + k0 + ac];
            }
        }
        int gn = colBase + bn;
        pbh = z4; pbl = z4;
        if (gn < N) {
            pbh = *(const uint4*)&Bhg[(size_t)gn * K + k0 + bc];
            pbl = *(const uint4*)&Blg[(size_t)gn * K + k0 + bc];
        }
    };
    auto storeT = [&]() {
#pragma unroll
        for (int p = 0; p < 2; p++) {
            int r = ar + p * 64;
            *(uint4*)&Ah[r][ac] = pah[p];
            *(uint4*)&Al[r][ac] = pal[p];
        }
        *(uint4*)&Bh[bn][bc] = pbh;
        *(uint4*)&Bl[bn][bc] = pbl;
    };

    loadT(0);

    for (int t = 0; t < nt; t++) {
        storeT();
        __syncthreads();
        if (t + 1 < nt) loadT(t + 1);   // overlap gmem latency with compute

#pragma unroll
        for (int ks = 0; ks < BK; ks += 16) {
            uint32_t ahf[2][4], alf[2][4], bhf[4][2], blf[4][2];
#pragma unroll
            for (int mi = 0; mi < 2; mi++) {
                int r0 = warpRow + mi * 16 + g;
                int r1 = r0 + 8;
                ahf[mi][0] = *(const uint32_t*)&Ah[r0][ks + t2];
                ahf[mi][1] = *(const uint32_t*)&Ah[r1][ks + t2];
                ahf[mi][2] = *(const uint32_t*)&Ah[r0][ks + t2 + 8];
                ahf[mi][3] = *(const uint32_t*)&Ah[r1][ks + t2 + 8];
                alf[mi][0] = *(const uint32_t*)&Al[r0][ks + t2];
                alf[mi][1] = *(const uint32_t*)&Al[r1][ks + t2];
                alf[mi][2] = *(const uint32_t*)&Al[r0][ks + t2 + 8];
                alf[mi][3] = *(const uint32_t*)&Al[r1][ks + t2 + 8];
            }
#pragma unroll
            for (int ni = 0; ni < 4; ni++) {
                int n = warpCol + ni * 8 + g;
                bhf[ni][0] = *(const uint32_t*)&Bh[n][ks + t2];
                bhf[ni][1] = *(const uint32_t*)&Bh[n][ks + t2 + 8];
                blf[ni][0] = *(const uint32_t*)&Bl[n][ks + t2];
                blf[ni][1] = *(const uint32_t*)&Bl[n][ks + t2 + 8];
            }
#pragma unroll
            for (int mi = 0; mi < 2; mi++)
#pragma unroll
                for (int ni = 0; ni < 4; ni++) {
                    mma_bf16(c[mi][ni], ahf[mi], bhf[ni]);
                    mma_bf16(c[mi][ni], ahf[mi], blf[ni]);
                    mma_bf16(c[mi][ni], alf[mi], bhf[ni]);
                }
        }
        if (t + 1 < nt) __syncthreads();
    }

    // --- epilogue ---
#pragma unroll
    for (int mi = 0; mi < 2; mi++) {
        int rm0 = rowBase + warpRow + mi * 16 + g;
        int rm1 = rm0 + 8;
#pragma unroll
        for (int ni = 0; ni < 4; ni++) {
            int cn = colBase + warpCol + ni * 8 + t2;
#pragma unroll
            for (int e = 0; e < 4; e++) {
                int gm = (e < 2) ? rm0 : rm1;
                int gn = cn + (e & 1);
                if (gm >= M || gn >= N) continue;
                float v = c[mi][ni][e];
                if (BIAS) v += bias[gn];
                if (GELU) v = 0.5f * v * (1.f + erff(v * 0.70710678118654752440f));
                if (HILO) {
                    __nv_bfloat16 h, l;
                    split_bf(v, h, l);
                    Chh[(size_t)gm * N + gn] = h;
                    Chl[(size_t)gm * N + gn] = l;
                } else {
                    C[(size_t)gm * N + gn] = v;
                }
            }
        }
    }
}

// ---------------------------------------------------------------------------
// Converters (run once per launch)
// ---------------------------------------------------------------------------
__global__ void xconv_kernel(const float* __restrict__ X)
{
    int i = blockIdx.x * 256 + threadIdx.x;
    if (i < NROWS_ALL * D) {
        __nv_bfloat16 h, l;
        split_bf(X[i], h, l);
        BF16P(F_XH)[i] = h;
        BF16P(F_XL)[i] = l;
    }
}

__global__ void wconv_kernel(const float* __restrict__ W, int K, int N,
                             size_t hioff, size_t elems)
{
    __shared__ float tile[32][33];
    __nv_bfloat16* Th = BF16P(hioff);
    __nv_bfloat16* Tl = Th + elems;
    int k0 = blockIdx.y * 32, n0 = blockIdx.x * 32;
    int tx = threadIdx.x, ty = threadIdx.y;   // 32 x 8
    for (int i = ty; i < 32; i += 8) {
        int k = k0 + i, n = n0 + tx;
        tile[i][tx] = (k < K && n < N) ? W[(size_t)k * N + n] : 0.f;
    }
    __syncthreads();
    for (int i = ty; i < 32; i += 8) {
        int n = n0 + i, k = k0 + tx;
        if (n < N && k < K) {
            __nv_bfloat16 h, l;
            split_bf(tile[tx][i], h, l);
            Th[(size_t)n * K + k] = h;
            Tl[(size_t)n * K + k] = l;
        }
    }
}

__device__ __forceinline__ float warpSum(float v) {
#pragma unroll
    for (int o = 16; o; o >>= 1) v += __shfl_down_sync(0xffffffffu, v, o);
    return v;
}

// ---------------------------------------------------------------------------
// Projector mask
// ---------------------------------------------------------------------------
__global__ void mask_kernel()
{
    const float* E = EBUF;
    const int idx = blockIdx.x;
    const int n = idx % 197;
    const int lane = threadIdx.x;
    const float* ex = E + (size_t)idx * H2;

    float ex0 = ex[lane], ex1 = ex[lane + 32], ex2 = ex[lane + 64];
    float s = ex0 * ex0 + ex1 * ex1 + ex2 * ex2;
    s = warpSum(s);
    float nx = fmaxf(sqrtf(s), 1e-8f);
    nx = __shfl_sync(0xffffffffu, nx, 0);

    float csum = 0.f;
#pragma unroll
    for (int r = 0; r < 10; r++) {
        const float* er = E + (size_t)(NROWS_M + r * 197 + n) * H2;
        float e0 = er[lane], e1 = er[lane + 32], e2 = er[lane + 64];
        float d  = ex0 * e0 + ex1 * e1 + ex2 * e2;
        float n2 = e0 * e0 + e1 * e1 + e2 * e2;
        d  = warpSum(d);
        n2 = warpSum(n2);
        if (lane == 0) {
            float nr = fmaxf(sqrtf(n2), 1e-8f);
            csum += d / (nx * nr);
        }
    }
    if (lane == 0) {
        float c = (csum * 0.1f + 1.f) * 0.5f;
        MASKB[idx] = 0.5f + 0.5f * tanhf(25.f * (c - 0.5f));
    }
}

// ---------------------------------------------------------------------------
// Gram: M_h = (1/10) * sum_n K[n,h]^T K[n,h]
// ---------------------------------------------------------------------------
__global__ void gram_kernel()
{
    const float* Kb = KBUF;
    const int h = blockIdx.x;
    __shared__ float Ks[32][HD];
    const int tid = threadIdx.x;
    const int tj = tid % 16, ti = tid / 16;
    float acc[4][4] = {};

    for (int n0 = 0; n0 < NROWS_R; n0 += 32) {
        for (int i = tid; i < 32 * HD; i += 256) {
            int r = i / HD, c = i % HD;
            int n = n0 + r;
            Ks[r][c] = (n < NROWS_R) ? Kb[(size_t)n * D + h * HD + c] : 0.f;
        }
        __syncthreads();
#pragma unroll
        for (int r = 0; r < 32; r++) {
            float a[4], b[4];
#pragma unroll
            for (int i = 0; i < 4; i++) a[i] = Ks[r][ti * 4 + i];
#pragma unroll
            for (int j = 0; j < 4; j++) b[j] = Ks[r][tj * 4 + j];
#pragma unroll
            for (int i = 0; i < 4; i++)
#pragma unroll
                for (int j = 0; j < 4; j++) acc[i][j] += a[i] * b[j];
        }
        __syncthreads();
    }
#pragma unroll
    for (int i = 0; i < 4; i++)
#pragma unroll
        for (int j = 0; j < 4; j++)
            MBUF[(size_t)h * HD * HD + (ti * 4 + i) * HD + (tj * 4 + j)] = acc[i][j] * 0.1f;
}

// ---------------------------------------------------------------------------
// Fused qtv + wmat: P = Q^T V (inner 197); W = (1/64) * M_h @ P.
// ---------------------------------------------------------------------------
__global__ __launch_bounds__(256) void qtv_wmat_kernel()
{
    const float* QV = QVBUF;
    const int bh = blockIdx.x;
    const int b = bh / NH, h = bh % NH;
    __shared__ float Qs[32][HD];
    __shared__ float Vs[32][HD];
    __shared__ float Ps[HD][HD];
    __shared__ float Ms[HD][HD];
    const int tid = threadIdx.x;
    const int tj = tid % 16, ti = tid / 16;
    float acc[4][4] = {};

    for (int n0 = 0; n0 < 197; n0 += 32) {
        for (int i = tid; i < 32 * HD; i += 256) {
            int r = i / HD, c = i % HD;
            int n = n0 + r;
            float q = 0.f, v = 0.f;
            if (n < 197) {
                size_t base = (size_t)(b * 197 + n) * (2 * D) + h * HD + c;
                q = QV[base];
                v = QV[base + D];
            }
            Qs[r][c] = q;
            Vs[r][c] = v;
        }
        __syncthreads();
#pragma unroll
        for (int r = 0; r < 32; r++) {
            float a[4], bv[4];
#pragma unroll
            for (int i = 0; i < 4; i++) a[i] = Qs[r][ti * 4 + i];
#pragma unroll
            for (int j = 0; j < 4; j++) bv[j] = Vs[r][tj * 4 + j];
#pragma unroll
            for (int i = 0; i < 4; i++)
#pragma unroll
                for (int j = 0; j < 4; j++) acc[i][j] += a[i] * bv[j];
        }
        __syncthreads();
    }

#pragma unroll
    for (int i = 0; i < 4; i++)
#pragma unroll
        for (int j = 0; j < 4; j++)
            Ps[ti * 4 + i][tj * 4 + j] = acc[i][j];
    for (int i = tid; i < HD * HD; i += 256)
        Ms[i >> 6][i & 63] = MBUF[(size_t)h * HD * HD + i];
    __syncthreads();

    float w[4][4] = {};
#pragma unroll 8
    for (int k = 0; k < HD; k++) {
        float a[4], bv[4];
#pragma unroll
        for (int i = 0; i < 4; i++) a[i] = Ms[ti * 4 + i][k];
#pragma unroll
        for (int j = 0; j < 4; j++) bv[j] = Ps[k][tj * 4 + j];
#pragma unroll
        for (int i = 0; i < 4; i++)
#pragma unroll
            for (int j = 0; j < 4; j++) w[i][j] += a[i] * bv[j];
    }
#pragma unroll
    for (int i = 0; i < 4; i++)
#pragma unroll
        for (int j = 0; j < 4; j++)
            WBUF[(size_t)bh * HD * HD + (ti * 4 + i) * HD + (tj * 4 + j)] =
                w[i][j] * (1.f / 64.f);
}

// ---------------------------------------------------------------------------
// Y(b,h,n,:) = Q(b,h,n,:) @ W[b,h]; scrambled (B,H,N,hd) write, hi/lo bf16.
// ---------------------------------------------------------------------------
__global__ void qw_kernel()
{
    const float* QV = QVBUF;
    const int bh = blockIdx.x;
    const int b = bh / NH, h = bh % NH;
    __shared__ float Ws[HD][HD];
    const int tid = threadIdx.x;
    for (int i = tid; i < HD * HD; i += 256)
        Ws[i / HD][i % HD] = WBUF[(size_t)bh * HD * HD + i];
    __syncthreads();

    const int lr = tid / 8;
    const int lc = (tid % 8) * 8;
    const int n = blockIdx.y * 32 + lr;
    if (n >= 197) return;

    const float* qrow = QV + (size_t)(b * 197 + n) * (2 * D) + h * HD;
    float acc[8] = {};
#pragma unroll 8
    for (int d = 0; d < HD; d++) {
        float q = qrow[d];
#pragma unroll
        for (int j = 0; j < 8; j++) acc[j] += q * Ws[d][lc + j];
    }
    size_t yoff = (size_t)b * (197 * D) + (size_t)h * (197 * HD)
                + (size_t)n * HD + lc;
#pragma unroll
    for (int j = 0; j < 8; j++) {
        __nv_bfloat16 hh, ll;
        split_bf(acc[j], hh, ll);
        BF16P(F_YH)[yoff + j] = hh;
        BF16P(F_YL)[yoff + j] = ll;
    }
}

// ---------------------------------------------------------------------------
// LayerNorm (768): ZBUF -> XC hi/lo
// ---------------------------------------------------------------------------
__global__ void ln_kernel(const float* __restrict__ g, const float* __restrict__ b)
{
    const int row = blockIdx.x;
    const float* z = ZBUF + (size_t)row * D;
    const int t = threadIdx.x;
    float v0 = z[t], v1 = z[t + 256], v2 = z[t + 512];
    float s = v0 + v1 + v2;
    float ss = v0 * v0 + v1 * v1 + v2 * v2;

    __shared__ float sh1[8], sh2[8];
    const int lane = t & 31, w = t >> 5;
    s = warpSum(s);
    ss = warpSum(ss);
    if (lane == 0) { sh1[w] = s; sh2[w] = ss; }
    __syncthreads();
    if (w == 0) {
        float a = lane < 8 ? sh1[lane] : 0.f;
        float c = lane < 8 ? sh2[lane] : 0.f;
        a = warpSum(a);
        c = warpSum(c);
        if (lane == 0) { sh1[0] = a; sh2[0] = c; }
    }
    __syncthreads();
    const float mu = sh1[0] * (1.f / 768.f);
    const float var = sh2[0] * (1.f / 768.f) - mu * mu;
    const float inv = rsqrtf(var + 1e-5f);
    size_t base = (size_t)row * D;
#pragma unroll
    for (int p = 0; p < 3; p++) {
        int idx = t + p * 256;
        float vv = (p == 0 ? v0 : (p == 1 ? v1 : v2));
        float o = (vv - mu) * inv * g[idx] + b[idx];
        __nv_bfloat16 hh, ll;
        split_bf(o, hh, ll);
        BF16P(F_XCH)[base + idx] = hh;
        BF16P(F_XCL)[base + idx] = ll;
    }
}

// ---------------------------------------------------------------------------
// Elementwise
// ---------------------------------------------------------------------------
__global__ void maskmul_kernel(const float* __restrict__ x)
{
    int i = blockIdx.x * blockDim.x + threadIdx.x;
    if (i < NROWS_M * D) {
        float v = x[i] * MASKB[i / D];
        __nv_bfloat16 hh, ll;
        split_bf(v, hh, ll);
        BF16P(F_XCH)[i] = hh;
        BF16P(F_XCL)[i] = ll;
    }
}

__global__ void blend_kernel(const float* __restrict__ x, float* __restrict__ out)
{
    int i = blockIdx.x * blockDim.x + threadIdx.x;
    if (i < NROWS_M * D) {
        float m = MASKB[i / D];
        float corr = __bfloat162float(BF16P(F_XCH)[i]) + __bfloat162float(BF16P(F_XCL)[i]);
        out[i] = m * corr + (1.f - m) * x[i];
    }
}

// ---------------------------------------------------------------------------
// Launch
// ---------------------------------------------------------------------------
extern "C" void kernel_launch(void* const* d_in, const int* in_sizes, int n_in,
                              void* d_out, int out_size)
{
    const float* x      = (const float*)d_in[0];
    const float* qv_w   = (const float*)d_in[1];
    const float* k_w    = (const float*)d_in[2];
    const float* proj_w = (const float*)d_in[3];
    const float* proj_b = (const float*)d_in[4];
    const float* ln_g   = (const float*)d_in[5];
    const float* ln_b   = (const float*)d_in[6];
    const float* fc1_w  = (const float*)d_in[7];
    const float* fc1_b  = (const float*)d_in[8];
    const float* fc2_w  = (const float*)d_in[9];
    const float* fc2_b  = (const float*)d_in[10];
    float* out = (float*)d_out;

    const float* ref = x + (size_t)NROWS_M * D;

    cudaMemcpyAsync(out + (size_t)NROWS_M * D, ref,
                    (size_t)NROWS_R * D * sizeof(float),
                    cudaMemcpyDeviceToDevice, 0);

    auto cdiv = [](int a, int b) { return (a + b - 1) / b; };

    // --- operand conversion (once) ---
    xconv_kernel<<<cdiv(NROWS_ALL * D, 256), 256>>>(x);
    dim3 wb(32, 8);
    wconv_kernel<<<dim3(cdiv(2 * D, 32), cdiv(D, 32)), wb>>>(qv_w, D, 2 * D, F_WQV, (size_t)2 * D * D);
    wconv_kernel<<<dim3(cdiv(D, 32), cdiv(D, 32)), wb>>>(k_w, D, D, F_WK, (size_t)D * D);
    wconv_kernel<<<dim3(cdiv(D, 32), cdiv(D, 32)), wb>>>(proj_w, D, D, F_WP, (size_t)D * D);
    wconv_kernel<<<dim3(cdiv(H1, 32), cdiv(D, 32)), wb>>>(fc1_w, D, H1, F_WF1, (size_t)H1 * D);
    wconv_kernel<<<dim3(cdiv(H2, 32), cdiv(H1, 32)), wb>>>(fc2_w, H1, H2, F_WF2, (size_t)H2 * H1);

    // --- projector encoder ---
    bgemm_kernel<true, true, true><<<dim3(cdiv(H1, 64), cdiv(NROWS_ALL, 128)), 256>>>(
        A_X, BW_F1, fc1_b, C_E, NROWS_ALL, H1, D);
    bgemm_kernel<true, false, false><<<dim3(cdiv(H2, 64), cdiv(NROWS_ALL, 128)), 256>>>(
        A_H, BW_F2, fc2_b, C_E, NROWS_ALL, H2, H1);
    mask_kernel<<<NROWS_M, 32>>>();

    // --- K projection + Gram ---
    bgemm_kernel<false, false, false><<<dim3(cdiv(D, 64), cdiv(NROWS_R, 128)), 256>>>(
        A_XREF, BW_K, nullptr, C_K, NROWS_R, D, D);
    gram_kernel<<<NH, 256>>>();

    // --- x0 = xm * mask (XC overwrites x-bf16 arena; safe after kproj) ---
    maskmul_kernel<<<(NROWS_M * D + 255) / 256, 256>>>(x);

    // --- 3 diffuser steps ---
    for (int step = 0; step < NSTEPS; step++) {
        bgemm_kernel<false, false, false><<<dim3(cdiv(2 * D, 64), cdiv(NROWS_M, 128)), 256>>>(
            A_XC, BW_QV, nullptr, C_QV, NROWS_M, 2 * D, D);
        qtv_wmat_kernel<<<8 * NH, 256>>>();
        qw_kernel<<<dim3(8 * NH, 7), 256>>>();
        bgemm_kernel<true, false, false><<<dim3(cdiv(D, 64), cdiv(NROWS_M, 128)), 256>>>(
            A_Y, BW_P, proj_b, C_Z, NROWS_M, D, D);
        ln_kernel<<<NROWS_M, 256>>>(ln_g, ln_b);
    }

    // --- final blend ---
    blend_kernel<<<(NROWS_M * D + 255) / 256, 256>>>(x, out);
}

// round 17
// speedup vs baseline: 2.7229x; 1.0184x over previous
#include <cuda_runtime.h>
#include <cuda_bf16.h>
#include <math.h>
#include <cstdint>

// ---------------------------------------------------------------------------
// TrustDiffuserModule — round 15: double-buffered smem GEMM (one sync per
// K-tile) with UNPADDED swizzled tiles: 49152 B = exactly the 48KB static cap.
//
// Math rewrite: mean_r (sQK_r^T)(sQK_r^T)^T V = Q * (s^2 * M * (Q^T V)),
// M = mean_r K_r^T K_r (64x64/head, once). Reference's (B,R,H,N,hd)->(B,R,N,C)
// reshape is a raw flatten (scrambled); reproduced by (B,H,N,hd) writes.
//
// GEMM precision: fp32 = hi + lo (bf16 each); C = Ah*Bh + Ah*Bl + Al*Bh.
// ---------------------------------------------------------------------------

#define NROWS_M   1576
#define NROWS_ALL 3546
#define NROWS_R   1970
#define D         768
#define H1        192
#define H2        96
#define NH        12
#define HD        64
#define NSTEPS    3

// ---- arena offsets (float units; liveness documented) ----
constexpr size_t F_WQV = 0;        // wqv hi+lo  (1,179,648 fl)
constexpr size_t F_WP  = 1179648;  // wp hi+lo   (589,824 fl)
constexpr size_t F_WK  = 1769472;  // wk hi+lo   (589,824 fl)   dead after kproj
constexpr size_t F_WF1 = 2359296;  // wf1 hi+lo  (147,456 fl)   dead after fc1
constexpr size_t F_WF2 = 2506752;  // wf2 hi+lo  (18,432 fl)    dead after fc2
constexpr size_t F_HB  = 2525184;  // H hi+lo    (680,832 fl)   dead after fc2
constexpr size_t F_Z   = F_WK;     // Z fp32 (1,210,368 fl) aliases wk..H
constexpr size_t F_XA  = 3206016;  // x arena (2,723,328 fl)
constexpr size_t F_XH  = F_XA;     //   x_hi; dead after kproj
constexpr size_t F_XL  = 4567680;  //   x_lo
constexpr size_t F_XCH = 3206016;  //   XC hi (after kproj)
constexpr size_t F_XCL = 3811200;  //   XC lo
constexpr size_t F_YH  = 4416384;  //   Y hi
constexpr size_t F_YL  = 5021568;  //   Y lo
constexpr size_t F_MASK= 5929344;
constexpr size_t F_M   = 5931392;
constexpr size_t F_W   = 5980544;
constexpr size_t F_QV  = 6373760;  // QV fp32 (2,420,736 fl)
constexpr size_t F_E   = F_QV;     //   E fp32 dead before step 1
constexpr size_t F_K   = 6714368;  //   K fp32 dead before step 1
constexpr size_t F_TOTAL = 8794496;  // 35.2 MB

__device__ float g_scratch[F_TOTAL];

#define BF16P(off) ((__nv_bfloat16*)(g_scratch + (off)))
#define MASKB (g_scratch + F_MASK)
#define KBUF  (g_scratch + F_K)
#define MBUF  (g_scratch + F_M)
#define QVBUF (g_scratch + F_QV)
#define EBUF  (g_scratch + F_E)
#define WBUF  (g_scratch + F_W)
#define ZBUF  (g_scratch + F_Z)

enum ASel { A_X = 0, A_XREF, A_H, A_XC, A_Y };
enum BSel { BW_QV = 0, BW_K, BW_P, BW_F1, BW_F2 };
enum CSel { C_K = 0, C_QV, C_Z, C_E };

__device__ __forceinline__ void aptr(int s, const __nv_bfloat16*& h, const __nv_bfloat16*& l) {
    switch (s) {
        case A_X:    h = BF16P(F_XH); l = BF16P(F_XL); break;
        case A_XREF: h = BF16P(F_XH) + (size_t)NROWS_M * D;
                     l = BF16P(F_XL) + (size_t)NROWS_M * D; break;
        case A_H:    h = BF16P(F_HB); l = BF16P(F_HB) + (size_t)NROWS_ALL * H1; break;
        case A_XC:   h = BF16P(F_XCH); l = BF16P(F_XCL); break;
        default:     h = BF16P(F_YH);  l = BF16P(F_YL);  break;
    }
}
__device__ __forceinline__ void bptr(int s, const __nv_bfloat16*& h, const __nv_bfloat16*& l) {
    switch (s) {
        case BW_QV: h = BF16P(F_WQV); l = BF16P(F_WQV) + (size_t)2 * D * D; break;
        case BW_K:  h = BF16P(F_WK);  l = BF16P(F_WK)  + (size_t)D * D;     break;
        case BW_P:  h = BF16P(F_WP);  l = BF16P(F_WP)  + (size_t)D * D;     break;
        case BW_F1: h = BF16P(F_WF1); l = BF16P(F_WF1) + (size_t)H1 * D;    break;
        default:    h = BF16P(F_WF2); l = BF16P(F_WF2) + (size_t)H2 * H1;   break;
    }
}
__device__ __forceinline__ float* cptr(int s) {
    switch (s) {
        case C_K:  return KBUF;
        case C_QV: return QVBUF;
        case C_Z:  return ZBUF;
        default:   return EBUF;
    }
}

__device__ __forceinline__ void split_bf(float v, __nv_bfloat16& h, __nv_bfloat16& l) {
    h = __float2bfloat16(v);
    l = __float2bfloat16(v - __bfloat162float(h));
}
__device__ __forceinline__ void mma_bf16(float* c, const uint32_t* a, const uint32_t* b) {
    asm volatile(
        "mma.sync.aligned.m16n8k16.row.col.f32.bf16.bf16.f32 "
        "{%0,%1,%2,%3}, {%4,%5,%6,%7}, {%8,%9}, {%0,%1,%2,%3};\n"
        : "+f"(c[0]), "+f"(c[1]), "+f"(c[2]), "+f"(c[3])
        : "r"(a[0]), "r"(a[1]), "r"(a[2]), "r"(a[3]), "r"(b[0]), "r"(b[1]));
}
// XOR swizzle: 8-byte groups (4 bf16) within a 64B row permuted by row&7.
// Conflict-free for both the uint2 staging stores and the 4B fragment loads.
__device__ __forceinline__ int swzc(int r, int c) {
    return ((((c >> 2) ^ (r & 7)) << 2) | (c & 3));
}

// ---------------------------------------------------------------------------
// Tensor-core GEMM: C[M,N] = A[M,K] @ Bt[N,K]^T, pre-split bf16 hi/lo.
// BM=128, BN=64, BK=32, 256 threads (8 warps as 4x2 -> 32x32 warp tiles).
// Double-buffered swizzled smem + register prefetch: ONE sync per K-tile.
// Smem: 2*(128+64)*32*2*2 = 49152 B (exactly the 48KB static cap).
// ---------------------------------------------------------------------------
template <bool BIAS, bool GELU, bool HILO>
__global__ __launch_bounds__(256)
void bgemm_kernel(int asel, int bsel, const float* __restrict__ bias,
                  int csel, int M, int N, int K)
{
    constexpr int BM = 128, BN = 64, BK = 32;
    const __nv_bfloat16 *Ahg, *Alg, *Bhg, *Blg;
    aptr(asel, Ahg, Alg);
    bptr(bsel, Bhg, Blg);
    float* C = cptr(csel);
    __nv_bfloat16* Chh = BF16P(F_HB);
    __nv_bfloat16* Chl = BF16P(F_HB) + (size_t)NROWS_ALL * H1;

    __shared__ __nv_bfloat16 Ah[2][BM][BK], Al[2][BM][BK];
    __shared__ __nv_bfloat16 Bh[2][BN][BK], Bl[2][BN][BK];

    const int tid  = threadIdx.x;
    const int wid  = tid >> 5;
    const int lane = tid & 31;
    const int g    = lane >> 2;       // 0..7
    const int t2   = (lane & 3) * 2;  // 0,2,4,6

    const int rowBase = blockIdx.y * BM;
    const int colBase = blockIdx.x * BN;
    const int warpRow = (wid >> 1) * 32;  // 0,32,64,96
    const int warpCol = (wid & 1) * 32;   // 0,32

    // stagers: uint4 = 8 bf16 from gmem; stored as 2x uint2 (swizzled)
    const int ar = tid >> 2;          // 0..63 (rows ar and ar+64)
    const int ac = (tid & 3) * 8;     // 0,8,16,24
    const int bn = tid >> 2;          // 0..63
    const int bc = (tid & 3) * 8;

    const int nt = K / BK;

    float c[2][4][4];
#pragma unroll
    for (int mi = 0; mi < 2; mi++)
#pragma unroll
        for (int ni = 0; ni < 4; ni++)
#pragma unroll
            for (int e = 0; e < 4; e++) c[mi][ni][e] = 0.f;

    uint4 pah[2], pal[2], pbh, pbl;
    const uint4 z4 = make_uint4(0u, 0u, 0u, 0u);

    auto loadT = [&](int t) {
        const int k0 = t * BK;
#pragma unroll
        for (int p = 0; p < 2; p++) {
            int gm = rowBase + ar + p * 64;
            pah[p] = z4; pal[p] = z4;
            if (gm < M) {
                pah[p] = *(const uint4*)&Ahg[(size_t)gm * K + k0 + ac];
                pal[p] = *(const uint4*)&Alg[(size_t)gm * K + k0 + ac];
            }
        }
        int gn = colBase + bn;
        pbh = z4; pbl = z4;
        if (gn < N) {
            pbh = *(const uint4*)&Bhg[(size_t)gn * K + k0 + bc];
            pbl = *(const uint4*)&Blg[(size_t)gn * K + k0 + bc];
        }
    };
    auto storeT = [&](int buf) {
#pragma unroll
        for (int p = 0; p < 2; p++) {
            int r = ar + p * 64;
            int c0 = swzc(r, ac), c1 = swzc(r, ac + 4);
            *(uint2*)&Ah[buf][r][c0] = make_uint2(pah[p].x, pah[p].y);
            *(uint2*)&Ah[buf][r][c1] = make_uint2(pah[p].z, pah[p].w);
            *(uint2*)&Al[buf][r][c0] = make_uint2(pal[p].x, pal[p].y);
            *(uint2*)&Al[buf][r][c1] = make_uint2(pal[p].z, pal[p].w);
        }
        int c0 = swzc(bn, bc), c1 = swzc(bn, bc + 4);
        *(uint2*)&Bh[buf][bn][c0] = make_uint2(pbh.x, pbh.y);
        *(uint2*)&Bh[buf][bn][c1] = make_uint2(pbh.z, pbh.w);
        *(uint2*)&Bl[buf][bn][c0] = make_uint2(pbl.x, pbl.y);
        *(uint2*)&Bl[buf][bn][c1] = make_uint2(pbl.z, pbl.w);
    };

    loadT(0);
    storeT(0);
    __syncthreads();

    for (int t = 0; t < nt; t++) {
        const int cur = t & 1;
        if (t + 1 < nt) loadT(t + 1);   // gmem -> regs, overlaps compute

#pragma unroll
        for (int ks = 0; ks < BK; ks += 16) {
            uint32_t ahf[2][4], alf[2][4], bhf[4][2], blf[4][2];
#pragma unroll
            for (int mi = 0; mi < 2; mi++) {
                int r0 = warpRow + mi * 16 + g;
                int r1 = r0 + 8;
                ahf[mi][0] = *(const uint32_t*)&Ah[cur][r0][swzc(r0, ks + t2)];
                ahf[mi][1] = *(const uint32_t*)&Ah[cur][r1][swzc(r1, ks + t2)];
                ahf[mi][2] = *(const uint32_t*)&Ah[cur][r0][swzc(r0, ks + t2 + 8)];
                ahf[mi][3] = *(const uint32_t*)&Ah[cur][r1][swzc(r1, ks + t2 + 8)];
                alf[mi][0] = *(const uint32_t*)&Al[cur][r0][swzc(r0, ks + t2)];
                alf[mi][1] = *(const uint32_t*)&Al[cur][r1][swzc(r1, ks + t2)];
                alf[mi][2] = *(const uint32_t*)&Al[cur][r0][swzc(r0, ks + t2 + 8)];
                alf[mi][3] = *(const uint32_t*)&Al[cur][r1][swzc(r1, ks + t2 + 8)];
            }
#pragma unroll
            for (int ni = 0; ni < 4; ni++) {
                int n = warpCol + ni * 8 + g;
                bhf[ni][0] = *(const uint32_t*)&Bh[cur][n][swzc(n, ks + t2)];
                bhf[ni][1] = *(const uint32_t*)&Bh[cur][n][swzc(n, ks + t2 + 8)];
                blf[ni][0] = *(const uint32_t*)&Bl[cur][n][swzc(n, ks + t2)];
                blf[ni][1] = *(const uint32_t*)&Bl[cur][n][swzc(n, ks + t2 + 8)];
            }
#pragma unroll
            for (int mi = 0; mi < 2; mi++)
#pragma unroll
                for (int ni = 0; ni < 4; ni++) {
                    mma_bf16(c[mi][ni], ahf[mi], bhf[ni]);
                    mma_bf16(c[mi][ni], ahf[mi], blf[ni]);
                    mma_bf16(c[mi][ni], alf[mi], bhf[ni]);
                }
        }
        if (t + 1 < nt) {
            storeT(cur ^ 1);   // buffer last computed at t-1; sync at t-1 protects it
            __syncthreads();
        }
    }

    // --- epilogue ---
#pragma unroll
    for (int mi = 0; mi < 2; mi++) {
        int rm0 = rowBase + warpRow + mi * 16 + g;
        int rm1 = rm0 + 8;
#pragma unroll
        for (int ni = 0; ni < 4; ni++) {
            int cn = colBase + warpCol + ni * 8 + t2;
#pragma unroll
            for (int e = 0; e < 4; e++) {
                int gm = (e < 2) ? rm0 : rm1;
                int gn = cn + (e & 1);
                if (gm >= M || gn >= N) continue;
                float v = c[mi][ni][e];
                if (BIAS) v += bias[gn];
                if (GELU) v = 0.5f * v * (1.f + erff(v * 0.70710678118654752440f));
                if (HILO) {
                    __nv_bfloat16 h, l;
                    split_bf(v, h, l);
                    Chh[(size_t)gm * N + gn] = h;
                    Chl[(size_t)gm * N + gn] = l;
                } else {
                    C[(size_t)gm * N + gn] = v;
                }
            }
        }
    }
}

// ---------------------------------------------------------------------------
// Converters (run once per launch)
// ---------------------------------------------------------------------------
__global__ void xconv_kernel(const float* __restrict__ X)
{
    int i = blockIdx.x * 256 + threadIdx.x;
    if (i < NROWS_ALL * D) {
        __nv_bfloat16 h, l;
        split_bf(X[i], h, l);
        BF16P(F_XH)[i] = h;
        BF16P(F_XL)[i] = l;
    }
}

__global__ void wconv_kernel(const float* __restrict__ W, int K, int N,
                             size_t hioff, size_t elems)
{
    __shared__ float tile[32][33];
    __nv_bfloat16* Th = BF16P(hioff);
    __nv_bfloat16* Tl = Th + elems;
    int k0 = blockIdx.y * 32, n0 = blockIdx.x * 32;
    int tx = threadIdx.x, ty = threadIdx.y;   // 32 x 8
    for (int i = ty; i < 32; i += 8) {
        int k = k0 + i, n = n0 + tx;
        tile[i][tx] = (k < K && n < N) ? W[(size_t)k * N + n] : 0.f;
    }
    __syncthreads();
    for (int i = ty; i < 32; i += 8) {
        int n = n0 + i, k = k0 + tx;
        if (n < N && k < K) {
            __nv_bfloat16 h, l;
            split_bf(tile[tx][i], h, l);
            Th[(size_t)n * K + k] = h;
            Tl[(size_t)n * K + k] = l;
        }
    }
}

__device__ __forceinline__ float warpSum(float v) {
#pragma unroll
    for (int o = 16; o; o >>= 1) v += __shfl_down_sync(0xffffffffu, v, o);
    return v;
}

// ---------------------------------------------------------------------------
// Projector mask
// ---------------------------------------------------------------------------
__global__ void mask_kernel()
{
    const float* E = EBUF;
    const int idx = blockIdx.x;
    const int n = idx % 197;
    const int lane = threadIdx.x;
    const float* ex = E + (size_t)idx * H2;

    float ex0 = ex[lane], ex1 = ex[lane + 32], ex2 = ex[lane + 64];
    float s = ex0 * ex0 + ex1 * ex1 + ex2 * ex2;
    s = warpSum(s);
    float nx = fmaxf(sqrtf(s), 1e-8f);
    nx = __shfl_sync(0xffffffffu, nx, 0);

    float csum = 0.f;
#pragma unroll
    for (int r = 0; r < 10; r++) {
        const float* er = E + (size_t)(NROWS_M + r * 197 + n) * H2;
        float e0 = er[lane], e1 = er[lane + 32], e2 = er[lane + 64];
        float d  = ex0 * e0 + ex1 * e1 + ex2 * e2;
        float n2 = e0 * e0 + e1 * e1 + e2 * e2;
        d  = warpSum(d);
        n2 = warpSum(n2);
        if (lane == 0) {
            float nr = fmaxf(sqrtf(n2), 1e-8f);
            csum += d / (nx * nr);
        }
    }
    if (lane == 0) {
        float c = (csum * 0.1f + 1.f) * 0.5f;
        MASKB[idx] = 0.5f + 0.5f * tanhf(25.f * (c - 0.5f));
    }
}

// ---------------------------------------------------------------------------
// Gram: M_h = (1/10) * sum_n K[n,h]^T K[n,h]
// ---------------------------------------------------------------------------
__global__ void gram_kernel()
{
    const float* Kb = KBUF;
    const int h = blockIdx.x;
    __shared__ float Ks[32][HD];
    const int tid = threadIdx.x;
    const int tj = tid % 16, ti = tid / 16;
    float acc[4][4] = {};

    for (int n0 = 0; n0 < NROWS_R; n0 += 32) {
        for (int i = tid; i < 32 * HD; i += 256) {
            int r = i / HD, c = i % HD;
            int n = n0 + r;
            Ks[r][c] = (n < NROWS_R) ? Kb[(size_t)n * D + h * HD + c] : 0.f;
        }
        __syncthreads();
#pragma unroll
        for (int r = 0; r < 32; r++) {
            float a[4], b[4];
#pragma unroll
            for (int i = 0; i < 4; i++) a[i] = Ks[r][ti * 4 + i];
#pragma unroll
            for (int j = 0; j < 4; j++) b[j] = Ks[r][tj * 4 + j];
#pragma unroll
            for (int i = 0; i < 4; i++)
#pragma unroll
                for (int j = 0; j < 4; j++) acc[i][j] += a[i] * b[j];
        }
        __syncthreads();
    }
#pragma unroll
    for (int i = 0; i < 4; i++)
#pragma unroll
        for (int j = 0; j < 4; j++)
            MBUF[(size_t)h * HD * HD + (ti * 4 + i) * HD + (tj * 4 + j)] = acc[i][j] * 0.1f;
}

// ---------------------------------------------------------------------------
// Fused qtv + wmat: P = Q^T V (inner 197); W = (1/64) * M_h @ P.
// ---------------------------------------------------------------------------
__global__ __launch_bounds__(256) void qtv_wmat_kernel()
{
    const float* QV = QVBUF;
    const int bh = blockIdx.x;
    const int b = bh / NH, h = bh % NH;
    __shared__ float Qs[32][HD];
    __shared__ float Vs[32][HD];
    __shared__ float Ps[HD][HD];
    __shared__ float Ms[HD][HD];
    const int tid = threadIdx.x;
    const int tj = tid % 16, ti = tid / 16;
    float acc[4][4] = {};

    for (int n0 = 0; n0 < 197; n0 += 32) {
        for (int i = tid; i < 32 * HD; i += 256) {
            int r = i / HD, c = i % HD;
            int n = n0 + r;
            float q = 0.f, v = 0.f;
            if (n < 197) {
                size_t base = (size_t)(b * 197 + n) * (2 * D) + h * HD + c;
                q = QV[base];
                v = QV[base + D];
            }
            Qs[r][c] = q;
            Vs[r][c] = v;
        }
        __syncthreads();
#pragma unroll
        for (int r = 0; r < 32; r++) {
            float a[4], bv[4];
#pragma unroll
            for (int i = 0; i < 4; i++) a[i] = Qs[r][ti * 4 + i];
#pragma unroll
            for (int j = 0; j < 4; j++) bv[j] = Vs[r][tj * 4 + j];
#pragma unroll
            for (int i = 0; i < 4; i++)
#pragma unroll
                for (int j = 0; j < 4; j++) acc[i][j] += a[i] * bv[j];
        }
        __syncthreads();
    }

#pragma unroll
    for (int i = 0; i < 4; i++)
#pragma unroll
        for (int j = 0; j < 4; j++)
            Ps[ti * 4 + i][tj * 4 + j] = acc[i][j];
    for (int i = tid; i < HD * HD; i += 256)
        Ms[i >> 6][i & 63] = MBUF[(size_t)h * HD * HD + i];
    __syncthreads();

    float w[4][4] = {};
#pragma unroll 8
    for (int k = 0; k < HD; k++) {
        float a[4], bv[4];
#pragma unroll
        for (int i = 0; i < 4; i++) a[i] = Ms[ti * 4 + i][k];
#pragma unroll
        for (int j = 0; j < 4; j++) bv[j] = Ps[k][tj * 4 + j];
#pragma unroll
        for (int i = 0; i < 4; i++)
#pragma unroll
            for (int j = 0; j < 4; j++) w[i][j] += a[i] * bv[j];
    }
#pragma unroll
    for (int i = 0; i < 4; i++)
#pragma unroll
        for (int j = 0; j < 4; j++)
            WBUF[(size_t)bh * HD * HD + (ti * 4 + i) * HD + (tj * 4 + j)] =
                w[i][j] * (1.f / 64.f);
}

// ---------------------------------------------------------------------------
// Y(b,h,n,:) = Q(b,h,n,:) @ W[b,h]; scrambled (B,H,N,hd) write, hi/lo bf16.
// ---------------------------------------------------------------------------
__global__ void qw_kernel()
{
    const float* QV = QVBUF;
    const int bh = blockIdx.x;
    const int b = bh / NH, h = bh % NH;
    __shared__ float Ws[HD][HD];
    const int tid = threadIdx.x;
    for (int i = tid; i < HD * HD; i += 256)
        Ws[i / HD][i % HD] = WBUF[(size_t)bh * HD * HD + i];
    __syncthreads();

    const int lr = tid / 8;
    const int lc = (tid % 8) * 8;
    const int n = blockIdx.y * 32 + lr;
    if (n >= 197) return;

    const float* qrow = QV + (size_t)(b * 197 + n) * (2 * D) + h * HD;
    float acc[8] = {};
#pragma unroll 8
    for (int d = 0; d < HD; d++) {
        float q = qrow[d];
#pragma unroll
        for (int j = 0; j < 8; j++) acc[j] += q * Ws[d][lc + j];
    }
    size_t yoff = (size_t)b * (197 * D) + (size_t)h * (197 * HD)
                + (size_t)n * HD + lc;
#pragma unroll
    for (int j = 0; j < 8; j++) {
        __nv_bfloat16 hh, ll;
        split_bf(acc[j], hh, ll);
        BF16P(F_YH)[yoff + j] = hh;
        BF16P(F_YL)[yoff + j] = ll;
    }
}

// ---------------------------------------------------------------------------
// LayerNorm (768): ZBUF -> XC hi/lo
// ---------------------------------------------------------------------------
__global__ void ln_kernel(const float* __restrict__ g, const float* __restrict__ b)
{
    const int row = blockIdx.x;
    const float* z = ZBUF + (size_t)row * D;
    const int t = threadIdx.x;
    float v0 = z[t], v1 = z[t + 256], v2 = z[t + 512];
    float s = v0 + v1 + v2;
    float ss = v0 * v0 + v1 * v1 + v2 * v2;

    __shared__ float sh1[8], sh2[8];
    const int lane = t & 31, w = t >> 5;
    s = warpSum(s);
    ss = warpSum(ss);
    if (lane == 0) { sh1[w] = s; sh2[w] = ss; }
    __syncthreads();
    if (w == 0) {
        float a = lane < 8 ? sh1[lane] : 0.f;
        float c = lane < 8 ? sh2[lane] : 0.f;
        a = warpSum(a);
        c = warpSum(c);
        if (lane == 0) { sh1[0] = a; sh2[0] = c; }
    }
    __syncthreads();
    const float mu = sh1[0] * (1.f / 768.f);
    const float var = sh2[0] * (1.f / 768.f) - mu * mu;
    const float inv = rsqrtf(var + 1e-5f);
    size_t base = (size_t)row * D;
#pragma unroll
    for (int p = 0; p < 3; p++) {
        int idx = t + p * 256;
        float vv = (p == 0 ? v0 : (p == 1 ? v1 : v2));
        float o = (vv - mu) * inv * g[idx] + b[idx];
        __nv_bfloat16 hh, ll;
        split_bf(o, hh, ll);
        BF16P(F_XCH)[base + idx] = hh;
        BF16P(F_XCL)[base + idx] = ll;
    }
}

// ---------------------------------------------------------------------------
// Elementwise
// ---------------------------------------------------------------------------
__global__ void maskmul_kernel(const float* __restrict__ x)
{
    int i = blockIdx.x * blockDim.x + threadIdx.x;
    if (i < NROWS_M * D) {
        float v = x[i] * MASKB[i / D];
        __nv_bfloat16 hh, ll;
        split_bf(v, hh, ll);
        BF16P(F_XCH)[i] = hh;
        BF16P(F_XCL)[i] = ll;
    }
}

__global__ void blend_kernel(const float* __restrict__ x, float* __restrict__ out)
{
    int i = blockIdx.x * blockDim.x + threadIdx.x;
    if (i < NROWS_M * D) {
        float m = MASKB[i / D];
        float corr = __bfloat162float(BF16P(F_XCH)[i]) + __bfloat162float(BF16P(F_XCL)[i]);
        out[i] = m * corr + (1.f - m) * x[i];
    }
}

// ---------------------------------------------------------------------------
// Launch
// ---------------------------------------------------------------------------
extern "C" void kernel_launch(void* const* d_in, const int* in_sizes, int n_in,
                              void* d_out, int out_size)
{
    const float* x      = (const float*)d_in[0];
    const float* qv_w   = (const float*)d_in[1];
    const float* k_w    = (const float*)d_in[2];
    const float* proj_w = (const float*)d_in[3];
    const float* proj_b = (const float*)d_in[4];
    const float* ln_g   = (const float*)d_in[5];
    const float* ln_b   = (const float*)d_in[6];
    const float* fc1_w  = (const float*)d_in[7];
    const float* fc1_b  = (const float*)d_in[8];
    const float* fc2_w  = (const float*)d_in[9];
    const float* fc2_b  = (const float*)d_in[10];
    float* out = (float*)d_out;

    const float* ref = x + (size_t)NROWS_M * D;

    cudaMemcpyAsync(out + (size_t)NROWS_M * D, ref,
                    (size_t)NROWS_R * D * sizeof(float),
                    cudaMemcpyDeviceToDevice, 0);

    auto cdiv = [](int a, int b) { return (a + b - 1) / b; };

    // --- operand conversion (once) ---
    xconv_kernel<<<cdiv(NROWS_ALL * D, 256), 256>>>(x);
    dim3 wb(32, 8);
    wconv_kernel<<<dim3(cdiv(2 * D, 32), cdiv(D, 32)), wb>>>(qv_w, D, 2 * D, F_WQV, (size_t)2 * D * D);
    wconv_kernel<<<dim3(cdiv(D, 32), cdiv(D, 32)), wb>>>(k_w, D, D, F_WK, (size_t)D * D);
    wconv_kernel<<<dim3(cdiv(D, 32), cdiv(D, 32)), wb>>>(proj_w, D, D, F_WP, (size_t)D * D);
    wconv_kernel<<<dim3(cdiv(H1, 32), cdiv(D, 32)), wb>>>(fc1_w, D, H1, F_WF1, (size_t)H1 * D);
    wconv_kernel<<<dim3(cdiv(H2, 32), cdiv(H1, 32)), wb>>>(fc2_w, H1, H2, F_WF2, (size_t)H2 * H1);

    // --- projector encoder ---
    bgemm_kernel<true, true, true><<<dim3(cdiv(H1, 64), cdiv(NROWS_ALL, 128)), 256>>>(
        A_X, BW_F1, fc1_b, C_E, NROWS_ALL, H1, D);
    bgemm_kernel<true, false, false><<<dim3(cdiv(H2, 64), cdiv(NROWS_ALL, 128)), 256>>>(
        A_H, BW_F2, fc2_b, C_E, NROWS_ALL, H2, H1);
    mask_kernel<<<NROWS_M, 32>>>();

    // --- K projection + Gram ---
    bgemm_kernel<false, false, false><<<dim3(cdiv(D, 64), cdiv(NROWS_R, 128)), 256>>>(
        A_XREF, BW_K, nullptr, C_K, NROWS_R, D, D);
    gram_kernel<<<NH, 256>>>();

    // --- x0 = xm * mask (XC overwrites x-bf16 arena; safe after kproj) ---
    maskmul_kernel<<<(NROWS_M * D + 255) / 256, 256>>>(x);

    // --- 3 diffuser steps ---
    for (int step = 0; step < NSTEPS; step++) {
        bgemm_kernel<false, false, false><<<dim3(cdiv(2 * D, 64), cdiv(NROWS_M, 128)), 256>>>(
            A_XC, BW_QV, nullptr, C_QV, NROWS_M, 2 * D, D);
        qtv_wmat_kernel<<<8 * NH, 256>>>();
        qw_kernel<<<dim3(8 * NH, 7), 256>>>();
        bgemm_kernel<true, false, false><<<dim3(cdiv(D, 64), cdiv(NROWS_M, 128)), 256>>>(
            A_Y, BW_P, proj_b, C_Z, NROWS_M, D, D);
        ln_kernel<<<NROWS_M, 256>>>(ln_g, ln_b);
    }

    // --- final blend ---
    blend_kernel<<<(NROWS_M * D + 255) / 256, 256>>>(x, out);
}